// round 1
// baseline (speedup 1.0000x reference)
#include <cuda_runtime.h>
#include <cuda_bf16.h>
#include <math.h>

#define S_LEN 3072
#define DMODEL 1280
#define NHEAD 16
#define HDIM 80
#define FFDIM 5120

// ---------------- scratch (device globals; no allocations allowed) ----------
__device__ float g_h[S_LEN * DMODEL];          // LN output
__device__ float g_qkv[S_LEN * 3 * DMODEL];    // QKV
__device__ float g_attn[S_LEN * DMODEL];       // attention output
__device__ float g_x1[S_LEN * DMODEL];         // x + proj(attn)
__device__ float g_ff[S_LEN * FFDIM];          // gelu(fc1)

// ---------------- LayerNorm ----------------
__global__ __launch_bounds__(256) void ln_kernel(
    const float* __restrict__ x, const float* __restrict__ sc,
    const float* __restrict__ bi, float* __restrict__ out)
{
    int row = blockIdx.x;
    const float* xr = x + row * DMODEL;
    float* orow = out + row * DMODEL;
    int t = threadIdx.x;
    float v[5];
    float s = 0.f, s2 = 0.f;
#pragma unroll
    for (int i = 0; i < 5; i++) {
        v[i] = xr[t + i * 256];
        s += v[i];
        s2 = fmaf(v[i], v[i], s2);
    }
    __shared__ float rs[8], rs2[8];
#pragma unroll
    for (int o = 16; o; o >>= 1) {
        s  += __shfl_xor_sync(0xffffffffu, s, o);
        s2 += __shfl_xor_sync(0xffffffffu, s2, o);
    }
    if ((t & 31) == 0) { rs[t >> 5] = s; rs2[t >> 5] = s2; }
    __syncthreads();
    if (t < 32) {
        float a = (t < 8) ? rs[t] : 0.f;
        float b = (t < 8) ? rs2[t] : 0.f;
#pragma unroll
        for (int o = 4; o; o >>= 1) {
            a += __shfl_xor_sync(0xffffffffu, a, o);
            b += __shfl_xor_sync(0xffffffffu, b, o);
        }
        if (t == 0) { rs[0] = a; rs2[0] = b; }
    }
    __syncthreads();
    float mu = rs[0] * (1.f / DMODEL);
    float var = rs2[0] * (1.f / DMODEL) - mu * mu;
    float inv = rsqrtf(var + 1e-6f);
#pragma unroll
    for (int i = 0; i < 5; i++) {
        int c = t + i * 256;
        orow[c] = (v[i] - mu) * inv * sc[c] + bi[c];
    }
}

// ---------------- SGEMM: C = A(MxK) @ B(KxN) + bias (+res) (+quickGELU) ----
template <int ACT, int RES>
__global__ __launch_bounds__(256) void gemm128(
    const float* __restrict__ A, const float* __restrict__ B,
    const float* __restrict__ bias, const float* __restrict__ res,
    float* __restrict__ C, int M, int N, int K)
{
    __shared__ float As[8][128];
    __shared__ float Bs[8][128];
    int row0 = blockIdx.y * 128, col0 = blockIdx.x * 128;
    int t = threadIdx.x;
    int tx = t & 15, ty = t >> 4;
    float acc[8][8];
#pragma unroll
    for (int i = 0; i < 8; i++)
#pragma unroll
        for (int j = 0; j < 8; j++) acc[i][j] = 0.f;

    int am = t >> 1;            // A row within tile
    int ak = (t & 1) * 4;       // A k offset
    int bk = t >> 5;            // B k row
    int bn = (t & 31) * 4;      // B col offset

    const float* aptr = A + (row0 + am) * K + ak;
    const float* bptr = B + bk * N + col0 + bn;

    for (int k0 = 0; k0 < K; k0 += 8) {
        float4 a4 = *(const float4*)(aptr + k0);
        As[ak + 0][am] = a4.x;
        As[ak + 1][am] = a4.y;
        As[ak + 2][am] = a4.z;
        As[ak + 3][am] = a4.w;
        *(float4*)(&Bs[bk][bn]) = *(const float4*)(bptr + (size_t)k0 * N);
        __syncthreads();
#pragma unroll
        for (int kk = 0; kk < 8; kk++) {
            float a[8], b[8];
            *(float4*)(a)     = *(const float4*)(&As[kk][ty * 8]);
            *(float4*)(a + 4) = *(const float4*)(&As[kk][ty * 8 + 4]);
            *(float4*)(b)     = *(const float4*)(&Bs[kk][tx * 8]);
            *(float4*)(b + 4) = *(const float4*)(&Bs[kk][tx * 8 + 4]);
#pragma unroll
            for (int i = 0; i < 8; i++)
#pragma unroll
                for (int j = 0; j < 8; j++)
                    acc[i][j] = fmaf(a[i], b[j], acc[i][j]);
        }
        __syncthreads();
    }
#pragma unroll
    for (int i = 0; i < 8; i++) {
        int m = row0 + ty * 8 + i;
        float* crow = C + (size_t)m * N;
        const float* rrow = RES ? (res + (size_t)m * N) : nullptr;
#pragma unroll
        for (int j = 0; j < 8; j++) {
            int n = col0 + tx * 8 + j;
            float v = acc[i][j] + bias[n];
            if (RES) v += rrow[n];
            if (ACT) v = v / (1.f + expf(-1.702f * v));
            crow[n] = v;
        }
    }
}

// ---------------- RoPE on q and k in-place ----------------
__global__ __launch_bounds__(256) void rope_kernel(
    float* __restrict__ qkv, const float* __restrict__ rot)
{
    int idx = blockIdx.x * 256 + threadIdx.x;   // over S*2*H*40
    const int total = S_LEN * 2 * NHEAD * 40;
    if (idx >= total) return;
    int i = idx % 40;
    int h = (idx / 40) % NHEAD;
    int w = (idx / (40 * NHEAD)) % 2;           // 0=q, 1=k
    int s = idx / (40 * NHEAD * 2);
    float* p = qkv + (size_t)s * (3 * DMODEL) + w * DMODEL + h * HDIM;
    float x1 = p[i];
    float x2 = p[i + 40];
    float f1 = rot[s * 40 + (i >> 1)];
    float f2 = rot[s * 40 + 20 + (i >> 1)];
    float c1, s1, c2, s2v;
    sincosf(f1, &s1, &c1);
    sincosf(f2, &s2v, &c2);
    p[i]      = x1 * c1 - x2 * s1;
    p[i + 40] = x2 * c2 + x1 * s2v;
}

// ---------------- Attention (block-diagonal segments) ----------------
// Block: 128 threads, handles one head x 16 query rows. Two-pass softmax with
// scores resident in shared memory; K/V staged through shared in 64-key tiles.
#define KSTR 81  // padded KV row stride (odd*... -> conflict-free kg*17 pattern)

__global__ __launch_bounds__(128) void attn_kernel(
    const float* __restrict__ qkv, const int* __restrict__ cu,
    int nseg, float* __restrict__ out)
{
    extern __shared__ float sm[];
    float* Qs  = sm;                  // 16*80
    float* KVs = sm + 16 * 80;        // 64*KSTR
    float* sc  = sm + 16 * 80 + 64 * KSTR;  // 16*1024

    const int t  = threadIdx.x;
    const int h  = blockIdx.y;
    const int q0 = blockIdx.x * 16;

    int start = 0, end = S_LEN;
    for (int i = 0; i < nseg; i++) {
        int a = cu[i], b = cu[i + 1];
        if (q0 >= a && q0 < b) { start = a; end = b; break; }
    }
    const int L = end - start;

    for (int idx = t; idx < 16 * 80; idx += 128) {
        int qi = idx / 80, d = idx - qi * 80;
        Qs[idx] = qkv[(size_t)(q0 + qi) * (3 * DMODEL) + h * HDIM + d];
    }
    __syncthreads();

    const float scale = rsqrtf((float)HDIM);
    const int kg = t & 31;   // this thread's keys: kg and kg+32
    const int qg = t >> 5;   // this thread's queries: 4*qg .. 4*qg+3

    // ---- Pass A: scores = Q K^T * scale ----
    for (int k0 = 0; k0 < L; k0 += 64) {
        const int kb = min(64, L - k0);
        for (int idx = t; idx < kb * 80; idx += 128) {
            int kk = idx / 80, d = idx - kk * 80;
            KVs[kk * KSTR + d] =
                qkv[(size_t)(start + k0 + kk) * (3 * DMODEL) + DMODEL + h * HDIM + d];
        }
        __syncthreads();
        float acc0[4] = {0.f, 0.f, 0.f, 0.f};
        float acc1[4] = {0.f, 0.f, 0.f, 0.f};
        const float* kr0 = KVs + kg * KSTR;
        const float* kr1 = KVs + (kg + 32) * KSTR;
        const float* qp  = Qs + (qg * 4) * 80;
#pragma unroll
        for (int d = 0; d < 80; d++) {
            float kv0 = kr0[d], kv1 = kr1[d];
#pragma unroll
            for (int j = 0; j < 4; j++) {
                float qv = qp[j * 80 + d];
                acc0[j] = fmaf(qv, kv0, acc0[j]);
                acc1[j] = fmaf(qv, kv1, acc1[j]);
            }
        }
#pragma unroll
        for (int j = 0; j < 4; j++) {
            int qi = qg * 4 + j;
            if (kg < kb)      sc[qi * 1024 + k0 + kg]      = acc0[j] * scale;
            if (kg + 32 < kb) sc[qi * 1024 + k0 + kg + 32] = acc1[j] * scale;
        }
        __syncthreads();
    }

    // ---- Pass B: row softmax (4 warps x 4 rows each) ----
    {
        int warp = t >> 5, lane = t & 31;
        for (int r = warp; r < 16; r += 4) {
            float* row = sc + r * 1024;
            float mx = -1e30f;
            for (int k = lane; k < L; k += 32) mx = fmaxf(mx, row[k]);
#pragma unroll
            for (int o = 16; o; o >>= 1) mx = fmaxf(mx, __shfl_xor_sync(0xffffffffu, mx, o));
            float sum = 0.f;
            for (int k = lane; k < L; k += 32) {
                float e = __expf(row[k] - mx);
                row[k] = e;
                sum += e;
            }
#pragma unroll
            for (int o = 16; o; o >>= 1) sum += __shfl_xor_sync(0xffffffffu, sum, o);
            float inv = 1.f / sum;
            for (int k = lane; k < L; k += 32) row[k] *= inv;
        }
    }
    __syncthreads();

    // ---- Pass C: out = P V ----
    const int td  = t & 15;   // d = td*5 .. td*5+4
    const int qg2 = t >> 4;   // qi = qg2 and qg2+8
    float oa[5] = {0.f, 0.f, 0.f, 0.f, 0.f};
    float ob[5] = {0.f, 0.f, 0.f, 0.f, 0.f};
    for (int k0 = 0; k0 < L; k0 += 64) {
        const int kb = min(64, L - k0);
        for (int idx = t; idx < kb * 80; idx += 128) {
            int kk = idx / 80, d = idx - kk * 80;
            KVs[kk * KSTR + d] =
                qkv[(size_t)(start + k0 + kk) * (3 * DMODEL) + 2 * DMODEL + h * HDIM + d];
        }
        __syncthreads();
        const float* p0 = sc + qg2 * 1024 + k0;
        const float* p1 = sc + (qg2 + 8) * 1024 + k0;
        for (int kk = 0; kk < kb; kk++) {
            float pa = p0[kk], pb = p1[kk];
            const float* vr = KVs + kk * KSTR + td * 5;
#pragma unroll
            for (int j = 0; j < 5; j++) {
                float vv = vr[j];
                oa[j] = fmaf(pa, vv, oa[j]);
                ob[j] = fmaf(pb, vv, ob[j]);
            }
        }
        __syncthreads();
    }
#pragma unroll
    for (int j = 0; j < 5; j++) {
        out[(size_t)(q0 + qg2) * DMODEL + h * HDIM + td * 5 + j]     = oa[j];
        out[(size_t)(q0 + qg2 + 8) * DMODEL + h * HDIM + td * 5 + j] = ob[j];
    }
}

// ---------------- launch ----------------
static float* sym_addr_f(const void* sym)
{
    void* p = nullptr;
    cudaGetSymbolAddress(&p, sym);
    return (float*)p;
}

extern "C" void kernel_launch(void* const* d_in, const int* in_sizes, int n_in,
                              void* d_out, int out_size)
{
    const float* x        = (const float*)d_in[0];
    const float* rot      = (const float*)d_in[1];
    const float* ln1_s    = (const float*)d_in[2];
    const float* ln1_b    = (const float*)d_in[3];
    const float* ln2_s    = (const float*)d_in[4];
    const float* ln2_b    = (const float*)d_in[5];
    const float* qkv_w    = (const float*)d_in[6];
    const float* qkv_b    = (const float*)d_in[7];
    const float* proj_w   = (const float*)d_in[8];
    const float* proj_b   = (const float*)d_in[9];
    const float* fc1_w    = (const float*)d_in[10];
    const float* fc1_b    = (const float*)d_in[11];
    const float* fc2_w    = (const float*)d_in[12];
    const float* fc2_b    = (const float*)d_in[13];
    const int*   cu       = (const int*)d_in[14];
    float*       out      = (float*)d_out;
    const int    nseg     = in_sizes[14] - 1;

    float* h    = sym_addr_f(g_h);
    float* qkv  = sym_addr_f(g_qkv);
    float* attn = sym_addr_f(g_attn);
    float* x1   = sym_addr_f(g_x1);
    float* ff   = sym_addr_f(g_ff);

    // attention dynamic shared: Qs + KVs + scores
    const int attn_smem = (16 * 80 + 64 * KSTR + 16 * 1024) * (int)sizeof(float);
    cudaFuncSetAttribute(attn_kernel, cudaFuncAttributeMaxDynamicSharedMemorySize, attn_smem);

    // 1) LN1
    ln_kernel<<<S_LEN, 256>>>(x, ln1_s, ln1_b, h);
    // 2) QKV = h @ qkv_w + b
    gemm128<0, 0><<<dim3(3 * DMODEL / 128, S_LEN / 128), 256>>>(
        h, qkv_w, qkv_b, nullptr, qkv, S_LEN, 3 * DMODEL, DMODEL);
    // 3) RoPE on q, k
    {
        int total = S_LEN * 2 * NHEAD * 40;
        rope_kernel<<<(total + 255) / 256, 256>>>(qkv, rot);
    }
    // 4) attention
    attn_kernel<<<dim3(S_LEN / 16, NHEAD), 128, attn_smem>>>(qkv, cu, nseg, attn);
    // 5) x1 = x + attn @ proj_w + proj_b
    gemm128<0, 1><<<dim3(DMODEL / 128, S_LEN / 128), 256>>>(
        attn, proj_w, proj_b, x, x1, S_LEN, DMODEL, DMODEL);
    // 6) LN2
    ln_kernel<<<S_LEN, 256>>>(x1, ln2_s, ln2_b, h);
    // 7) ff = quick_gelu(h @ fc1_w + fc1_b)
    gemm128<1, 0><<<dim3(FFDIM / 128, S_LEN / 128), 256>>>(
        h, fc1_w, fc1_b, nullptr, ff, S_LEN, FFDIM, DMODEL);
    // 8) out = x1 + ff @ fc2_w + fc2_b
    gemm128<0, 1><<<dim3(DMODEL / 128, S_LEN / 128), 256>>>(
        ff, fc2_w, fc2_b, x1, out, S_LEN, DMODEL, FFDIM);
}

// round 6
// speedup vs baseline: 1.6816x; 1.6816x over previous
#include <cuda_runtime.h>
#include <cuda_bf16.h>
#include <math.h>
#include <stdint.h>

#define S_LEN 3072
#define DMODEL 1280
#define NHEAD 16
#define HDIM 80
#define FFDIM 5120

// ---------------- scratch (device globals; no allocations allowed) ----------
__device__ float g_h[S_LEN * DMODEL];          // LN output (tf32-rounded)
__device__ float g_qkv[S_LEN * 3 * DMODEL];    // QKV
__device__ float g_attn[S_LEN * DMODEL];       // attention output (tf32-rounded)
__device__ float g_x1[S_LEN * DMODEL];         // x + proj(attn)
__device__ float g_ff[S_LEN * FFDIM];          // gelu(fc1) (tf32-rounded)
__device__ float g_wr_qkv[DMODEL * 3 * DMODEL];   // rounded weights [K,N]
__device__ float g_wr_proj[DMODEL * DMODEL];
__device__ float g_wr_fc1[DMODEL * FFDIM];
__device__ float g_wr_fc2[FFDIM * DMODEL];

// ---------------- helpers ----------------
__device__ __forceinline__ uint32_t smem_u32(const void* p) {
    uint32_t a;
    asm("{ .reg .u64 t; cvta.to.shared.u64 t, %1; cvt.u32.u64 %0, t; }"
        : "=r"(a) : "l"(p));
    return a;
}

__device__ __forceinline__ float tf32r(float x) {
    uint32_t u;
    asm("cvt.rna.tf32.f32 %0, %1;" : "=r"(u) : "f"(x));
    return __uint_as_float(u);
}

#define CP_ASYNC16(dst, src) \
    asm volatile("cp.async.cg.shared.global [%0], [%1], 16;" :: "r"(dst), "l"(src) : "memory")
#define CP_COMMIT() asm volatile("cp.async.commit_group;" ::: "memory")
#define CP_WAIT2()  asm volatile("cp.async.wait_group 2;" ::: "memory")

__device__ __forceinline__ void mma_tf32(float* c, const uint32_t* a, const uint32_t* b) {
    asm volatile(
        "mma.sync.aligned.m16n8k8.row.col.f32.tf32.tf32.f32 "
        "{%0,%1,%2,%3}, {%4,%5,%6,%7}, {%8,%9}, {%0,%1,%2,%3};"
        : "+f"(c[0]), "+f"(c[1]), "+f"(c[2]), "+f"(c[3])
        : "r"(a[0]), "r"(a[1]), "r"(a[2]), "r"(a[3]), "r"(b[0]), "r"(b[1]));
}

// ---------------- weight rounding (RNA tf32, elementwise) ----------------
__global__ __launch_bounds__(256) void round_tf32_kernel(
    const float* __restrict__ in, float* __restrict__ out, int n4)
{
    int i = blockIdx.x * 256 + threadIdx.x;
    if (i >= n4) return;
    float4 v = ((const float4*)in)[i];
    v.x = tf32r(v.x); v.y = tf32r(v.y); v.z = tf32r(v.z); v.w = tf32r(v.w);
    ((float4*)out)[i] = v;
}

// ---------------- tf32 mma.sync GEMM: C = A[M,K] @ B[K,N] + bias ----------
// BM=128, BN=128, BK=32, 4 stages, 256 threads (8 warps, 2x4), warp tile 64x32.
#define ASTR 36           // A smem row stride in floats (144 B)
#define BSTR 136          // B smem row stride in floats (544 B)
#define A_BYTES (128 * ASTR * 4)     // 18432
#define B_BYTES (32 * BSTR * 4)      // 17408
#define STG_BYTES (A_BYTES + B_BYTES)  // 35840
#define NSTAGE 4

template <int ACT, int RES, int ROUND>
__global__ __launch_bounds__(256, 1)
void gemm_mma(const float* __restrict__ A, const float* __restrict__ B,
              const float* __restrict__ bias, const float* __restrict__ res,
              float* __restrict__ C, int M, int N, int K)
{
    extern __shared__ __align__(16) char smem[];
    const uint32_t sb = smem_u32(smem);
    const int tid = threadIdx.x;
    const int wid = tid >> 5, lane = tid & 31;
    const int g = lane >> 2, t = lane & 3;
    const int warp_m = (wid >> 2) * 64;
    const int warp_n = (wid & 3) * 32;
    const int m0 = blockIdx.y * 128;
    const int n0 = blockIdx.x * 128;
    const int nk = K / 32;

    float c[4][4][4];
#pragma unroll
    for (int mt = 0; mt < 4; mt++)
#pragma unroll
        for (int nt = 0; nt < 4; nt++)
#pragma unroll
            for (int i = 0; i < 4; i++) c[mt][nt][i] = 0.f;

    // ---- async tile loader ----
    auto load_tile = [&](int stage, int k0) {
        uint32_t sA = sb + (uint32_t)stage * STG_BYTES;
        uint32_t sB = sA + A_BYTES;
#pragma unroll
        for (int cc = 0; cc < 4; cc++) {
            int idx = tid + cc * 256;            // 0..1023
            int row = idx >> 3, off = idx & 7;   // A: 128 rows x 8 chunks
            CP_ASYNC16(sA + (uint32_t)row * 144 + (uint32_t)off * 16,
                       (const char*)(A + (size_t)(m0 + row) * K + k0 + off * 4));
        }
#pragma unroll
        for (int cc = 0; cc < 4; cc++) {
            int idx = tid + cc * 256;
            int row = idx >> 5, off = idx & 31;  // B: 32 rows x 32 chunks
            CP_ASYNC16(sB + (uint32_t)row * 544 + (uint32_t)off * 16,
                       (const char*)(B + (size_t)(k0 + row) * N + n0 + off * 4));
        }
    };

    int k0 = 0;
#pragma unroll
    for (int s = 0; s < NSTAGE - 1; s++) {
        load_tile(s, k0);
        CP_COMMIT();
        k0 += 32;
    }

    for (int it = 0; it < nk; it++) {
        CP_WAIT2();
        __syncthreads();
        const int cur = it & (NSTAGE - 1);
        if (k0 < K) {
            load_tile((it + NSTAGE - 1) & (NSTAGE - 1), k0);
            k0 += 32;
        }
        CP_COMMIT();

        const float* As = (const float*)(smem + (size_t)cur * STG_BYTES);
        const float* Bs = (const float*)(smem + (size_t)cur * STG_BYTES + A_BYTES);

#pragma unroll
        for (int kk8 = 0; kk8 < 4; kk8++) {
            const int kk = kk8 * 8;
            uint32_t a[4][4], b[4][2];
#pragma unroll
            for (int mt = 0; mt < 4; mt++) {
                const float* ap = As + (warp_m + mt * 16 + g) * ASTR + kk + t;
                a[mt][0] = __float_as_uint(ap[0]);
                a[mt][2] = __float_as_uint(ap[4]);
                a[mt][1] = __float_as_uint(ap[8 * ASTR]);
                a[mt][3] = __float_as_uint(ap[8 * ASTR + 4]);
            }
#pragma unroll
            for (int nt = 0; nt < 4; nt++) {
                const float* bp = Bs + (kk + t) * BSTR + warp_n + nt * 8 + g;
                b[nt][0] = __float_as_uint(bp[0]);
                b[nt][1] = __float_as_uint(bp[4 * BSTR]);
            }
#pragma unroll
            for (int mt = 0; mt < 4; mt++)
#pragma unroll
                for (int nt = 0; nt < 4; nt++)
                    mma_tf32(c[mt][nt], a[mt], b[nt]);
        }
    }

    // ---- epilogue ----
#pragma unroll
    for (int mt = 0; mt < 4; mt++) {
        const int rm = m0 + warp_m + mt * 16 + g;
#pragma unroll
        for (int nt = 0; nt < 4; nt++) {
            const int cn = n0 + warp_n + nt * 8 + 2 * t;
            float2 bv = *(const float2*)(bias + cn);
            float v0 = c[mt][nt][0] + bv.x;
            float v1 = c[mt][nt][1] + bv.y;
            float v2 = c[mt][nt][2] + bv.x;
            float v3 = c[mt][nt][3] + bv.y;
            if (RES) {
                float2 r0 = *(const float2*)(res + (size_t)rm * N + cn);
                float2 r1 = *(const float2*)(res + (size_t)(rm + 8) * N + cn);
                v0 += r0.x; v1 += r0.y; v2 += r1.x; v3 += r1.y;
            }
            if (ACT) {
                v0 = v0 / (1.f + __expf(-1.702f * v0));
                v1 = v1 / (1.f + __expf(-1.702f * v1));
                v2 = v2 / (1.f + __expf(-1.702f * v2));
                v3 = v3 / (1.f + __expf(-1.702f * v3));
            }
            if (ROUND) {
                v0 = tf32r(v0); v1 = tf32r(v1); v2 = tf32r(v2); v3 = tf32r(v3);
            }
            *(float2*)(C + (size_t)rm * N + cn)       = make_float2(v0, v1);
            *(float2*)(C + (size_t)(rm + 8) * N + cn) = make_float2(v2, v3);
        }
    }
}

// ---------------- LayerNorm (tf32-rounded output) ----------------
__global__ __launch_bounds__(256) void ln_kernel(
    const float* __restrict__ x, const float* __restrict__ sc,
    const float* __restrict__ bi, float* __restrict__ out)
{
    int row = blockIdx.x;
    const float* xr = x + row * DMODEL;
    float* orow = out + row * DMODEL;
    int t = threadIdx.x;
    float v[5];
    float s = 0.f, s2 = 0.f;
#pragma unroll
    for (int i = 0; i < 5; i++) {
        v[i] = xr[t + i * 256];
        s += v[i];
        s2 = fmaf(v[i], v[i], s2);
    }
    __shared__ float rs[8], rs2[8];
#pragma unroll
    for (int o = 16; o; o >>= 1) {
        s  += __shfl_xor_sync(0xffffffffu, s, o);
        s2 += __shfl_xor_sync(0xffffffffu, s2, o);
    }
    if ((t & 31) == 0) { rs[t >> 5] = s; rs2[t >> 5] = s2; }
    __syncthreads();
    if (t < 32) {
        float a = (t < 8) ? rs[t] : 0.f;
        float b = (t < 8) ? rs2[t] : 0.f;
#pragma unroll
        for (int o = 4; o; o >>= 1) {
            a += __shfl_xor_sync(0xffffffffu, a, o);
            b += __shfl_xor_sync(0xffffffffu, b, o);
        }
        if (t == 0) { rs[0] = a; rs2[0] = b; }
    }
    __syncthreads();
    float mu = rs[0] * (1.f / DMODEL);
    float var = rs2[0] * (1.f / DMODEL) - mu * mu;
    float inv = rsqrtf(var + 1e-6f);
#pragma unroll
    for (int i = 0; i < 5; i++) {
        int c = t + i * 256;
        orow[c] = tf32r((v[i] - mu) * inv * sc[c] + bi[c]);
    }
}

// ---------------- RoPE on q and k in-place ----------------
__global__ __launch_bounds__(256) void rope_kernel(
    float* __restrict__ qkv, const float* __restrict__ rot)
{
    int idx = blockIdx.x * 256 + threadIdx.x;
    const int total = S_LEN * 2 * NHEAD * 40;
    if (idx >= total) return;
    int i = idx % 40;
    int h = (idx / 40) % NHEAD;
    int w = (idx / (40 * NHEAD)) % 2;
    int s = idx / (40 * NHEAD * 2);
    float* p = qkv + (size_t)s * (3 * DMODEL) + w * DMODEL + h * HDIM;
    float x1 = p[i];
    float x2 = p[i + 40];
    float f1 = rot[s * 40 + (i >> 1)];
    float f2 = rot[s * 40 + 20 + (i >> 1)];
    float c1, s1, c2, s2v;
    sincosf(f1, &s1, &c1);
    sincosf(f2, &s2v, &c2);
    p[i]      = x1 * c1 - x2 * s1;
    p[i + 40] = x2 * c2 + x1 * s2v;
}

// ---------------- Attention (block-diagonal segments) ----------------
#define KSTR 81

__global__ __launch_bounds__(128) void attn_kernel(
    const float* __restrict__ qkv, const int* __restrict__ cu,
    int nseg, float* __restrict__ out)
{
    extern __shared__ float sm[];
    float* Qs  = sm;
    float* KVs = sm + 16 * 80;
    float* sc  = sm + 16 * 80 + 64 * KSTR;

    const int t  = threadIdx.x;
    const int h  = blockIdx.y;
    const int q0 = blockIdx.x * 16;

    int start = 0, end = S_LEN;
    for (int i = 0; i < nseg; i++) {
        int a = cu[i], b = cu[i + 1];
        if (q0 >= a && q0 < b) { start = a; end = b; break; }
    }
    const int L = end - start;

    for (int idx = t; idx < 16 * 80; idx += 128) {
        int qi = idx / 80, d = idx - qi * 80;
        Qs[idx] = qkv[(size_t)(q0 + qi) * (3 * DMODEL) + h * HDIM + d];
    }
    __syncthreads();

    const float scale = rsqrtf((float)HDIM);
    const int kg = t & 31;
    const int qg = t >> 5;

    for (int k0 = 0; k0 < L; k0 += 64) {
        const int kb = min(64, L - k0);
        for (int idx = t; idx < kb * 80; idx += 128) {
            int kk = idx / 80, d = idx - kk * 80;
            KVs[kk * KSTR + d] =
                qkv[(size_t)(start + k0 + kk) * (3 * DMODEL) + DMODEL + h * HDIM + d];
        }
        __syncthreads();
        float acc0[4] = {0.f, 0.f, 0.f, 0.f};
        float acc1[4] = {0.f, 0.f, 0.f, 0.f};
        const float* kr0 = KVs + kg * KSTR;
        const float* kr1 = KVs + (kg + 32) * KSTR;
        const float* qp  = Qs + (qg * 4) * 80;
#pragma unroll
        for (int d = 0; d < 80; d++) {
            float kv0 = kr0[d], kv1 = kr1[d];
#pragma unroll
            for (int j = 0; j < 4; j++) {
                float qv = qp[j * 80 + d];
                acc0[j] = fmaf(qv, kv0, acc0[j]);
                acc1[j] = fmaf(qv, kv1, acc1[j]);
            }
        }
#pragma unroll
        for (int j = 0; j < 4; j++) {
            int qi = qg * 4 + j;
            if (kg < kb)      sc[qi * 1024 + k0 + kg]      = acc0[j] * scale;
            if (kg + 32 < kb) sc[qi * 1024 + k0 + kg + 32] = acc1[j] * scale;
        }
        __syncthreads();
    }

    {
        int warp = t >> 5, lane = t & 31;
        for (int r = warp; r < 16; r += 4) {
            float* row = sc + r * 1024;
            float mx = -1e30f;
            for (int k = lane; k < L; k += 32) mx = fmaxf(mx, row[k]);
#pragma unroll
            for (int o = 16; o; o >>= 1) mx = fmaxf(mx, __shfl_xor_sync(0xffffffffu, mx, o));
            float sum = 0.f;
            for (int k = lane; k < L; k += 32) {
                float e = __expf(row[k] - mx);
                row[k] = e;
                sum += e;
            }
#pragma unroll
            for (int o = 16; o; o >>= 1) sum += __shfl_xor_sync(0xffffffffu, sum, o);
            float inv = 1.f / sum;
            for (int k = lane; k < L; k += 32) row[k] *= inv;
        }
    }
    __syncthreads();

    const int td  = t & 15;
    const int qg2 = t >> 4;
    float oa[5] = {0.f, 0.f, 0.f, 0.f, 0.f};
    float ob[5] = {0.f, 0.f, 0.f, 0.f, 0.f};
    for (int k0 = 0; k0 < L; k0 += 64) {
        const int kb = min(64, L - k0);
        for (int idx = t; idx < kb * 80; idx += 128) {
            int kk = idx / 80, d = idx - kk * 80;
            KVs[kk * KSTR + d] =
                qkv[(size_t)(start + k0 + kk) * (3 * DMODEL) + 2 * DMODEL + h * HDIM + d];
        }
        __syncthreads();
        const float* p0 = sc + qg2 * 1024 + k0;
        const float* p1 = sc + (qg2 + 8) * 1024 + k0;
        for (int kk = 0; kk < kb; kk++) {
            float pa = p0[kk], pb = p1[kk];
            const float* vr = KVs + kk * KSTR + td * 5;
#pragma unroll
            for (int j = 0; j < 5; j++) {
                float vv = vr[j];
                oa[j] = fmaf(pa, vv, oa[j]);
                ob[j] = fmaf(pb, vv, ob[j]);
            }
        }
        __syncthreads();
    }
#pragma unroll
    for (int j = 0; j < 5; j++) {
        out[(size_t)(q0 + qg2) * DMODEL + h * HDIM + td * 5 + j]     = tf32r(oa[j]);
        out[(size_t)(q0 + qg2 + 8) * DMODEL + h * HDIM + td * 5 + j] = tf32r(ob[j]);
    }
}

// ---------------- launch ----------------
static float* sym_addr_f(const void* sym)
{
    void* p = nullptr;
    cudaGetSymbolAddress(&p, sym);
    return (float*)p;
}

extern "C" void kernel_launch(void* const* d_in, const int* in_sizes, int n_in,
                              void* d_out, int out_size)
{
    const float* x        = (const float*)d_in[0];
    const float* rot      = (const float*)d_in[1];
    const float* ln1_s    = (const float*)d_in[2];
    const float* ln1_b    = (const float*)d_in[3];
    const float* ln2_s    = (const float*)d_in[4];
    const float* ln2_b    = (const float*)d_in[5];
    const float* qkv_w    = (const float*)d_in[6];
    const float* qkv_b    = (const float*)d_in[7];
    const float* proj_w   = (const float*)d_in[8];
    const float* proj_b   = (const float*)d_in[9];
    const float* fc1_w    = (const float*)d_in[10];
    const float* fc1_b    = (const float*)d_in[11];
    const float* fc2_w    = (const float*)d_in[12];
    const float* fc2_b    = (const float*)d_in[13];
    const int*   cu       = (const int*)d_in[14];
    float*       out      = (float*)d_out;
    const int    nseg     = in_sizes[14] - 1;

    float* h     = sym_addr_f(g_h);
    float* qkv   = sym_addr_f(g_qkv);
    float* attn  = sym_addr_f(g_attn);
    float* x1    = sym_addr_f(g_x1);
    float* ff    = sym_addr_f(g_ff);
    float* wqkv  = sym_addr_f(g_wr_qkv);
    float* wproj = sym_addr_f(g_wr_proj);
    float* wfc1  = sym_addr_f(g_wr_fc1);
    float* wfc2  = sym_addr_f(g_wr_fc2);

    const int attn_smem = (16 * 80 + 64 * KSTR + 16 * 1024) * (int)sizeof(float);
    cudaFuncSetAttribute(attn_kernel, cudaFuncAttributeMaxDynamicSharedMemorySize, attn_smem);
    const int gemm_smem = NSTAGE * STG_BYTES;  // 143360
    cudaFuncSetAttribute(gemm_mma<0, 0, 0>, cudaFuncAttributeMaxDynamicSharedMemorySize, gemm_smem);
    cudaFuncSetAttribute(gemm_mma<0, 1, 0>, cudaFuncAttributeMaxDynamicSharedMemorySize, gemm_smem);
    cudaFuncSetAttribute(gemm_mma<1, 0, 1>, cudaFuncAttributeMaxDynamicSharedMemorySize, gemm_smem);

    // 0) weight rounding to tf32 (RNA) — no transpose needed for mma.sync
    {
        int n;
        n = DMODEL * 3 * DMODEL / 4;
        round_tf32_kernel<<<(n + 255) / 256, 256>>>(qkv_w, wqkv, n);
        n = DMODEL * DMODEL / 4;
        round_tf32_kernel<<<(n + 255) / 256, 256>>>(proj_w, wproj, n);
        n = DMODEL * FFDIM / 4;
        round_tf32_kernel<<<(n + 255) / 256, 256>>>(fc1_w, wfc1, n);
        n = FFDIM * DMODEL / 4;
        round_tf32_kernel<<<(n + 255) / 256, 256>>>(fc2_w, wfc2, n);
    }

    // 1) LN1 (tf32-rounded)
    ln_kernel<<<S_LEN, 256>>>(x, ln1_s, ln1_b, h);
    // 2) QKV = h @ qkv_w + b
    gemm_mma<0, 0, 0><<<dim3(3 * DMODEL / 128, S_LEN / 128), 256, gemm_smem>>>(
        h, wqkv, qkv_b, nullptr, qkv, S_LEN, 3 * DMODEL, DMODEL);
    // 3) RoPE
    {
        int total = S_LEN * 2 * NHEAD * 40;
        rope_kernel<<<(total + 255) / 256, 256>>>(qkv, rot);
    }
    // 4) attention
    attn_kernel<<<dim3(S_LEN / 16, NHEAD), 128, attn_smem>>>(qkv, cu, nseg, attn);
    // 5) x1 = x + attn @ proj_w + proj_b
    gemm_mma<0, 1, 0><<<dim3(DMODEL / 128, S_LEN / 128), 256, gemm_smem>>>(
        attn, wproj, proj_b, x, x1, S_LEN, DMODEL, DMODEL);
    // 6) LN2
    ln_kernel<<<S_LEN, 256>>>(x1, ln2_s, ln2_b, h);
    // 7) ff = quick_gelu(h @ fc1_w + fc1_b)  (tf32-rounded)
    gemm_mma<1, 0, 1><<<dim3(FFDIM / 128, S_LEN / 128), 256, gemm_smem>>>(
        h, wfc1, fc1_b, nullptr, ff, S_LEN, FFDIM, DMODEL);
    // 8) out = x1 + ff @ fc2_w + fc2_b
    gemm_mma<0, 1, 0><<<dim3(DMODEL / 128, S_LEN / 128), 256, gemm_smem>>>(
        ff, wfc2, fc2_b, x1, out, S_LEN, DMODEL, FFDIM);
}

// round 8
// speedup vs baseline: 4.6272x; 2.7517x over previous
#include <cuda_runtime.h>
#include <cuda_bf16.h>
#include <math.h>
#include <stdint.h>

#define S_LEN 3072
#define DMODEL 1280
#define NHEAD 16
#define HDIM 80
#define FFDIM 5120

// ---------------- scratch (device globals; no allocations allowed) ----------
__device__ float g_h[S_LEN * DMODEL];          // LN output (tf32-rounded)
__device__ float g_qkv[S_LEN * 3 * DMODEL];    // QKV (tf32-rounded)
__device__ float g_attn[S_LEN * DMODEL];       // attention output (tf32-rounded)
__device__ float g_x1[S_LEN * DMODEL];         // x + proj(attn)
__device__ float g_ff[S_LEN * FFDIM];          // gelu(fc1) (tf32-rounded)
__device__ float g_wr_qkv[DMODEL * 3 * DMODEL];   // rounded weights [K,N]
__device__ float g_wr_proj[DMODEL * DMODEL];
__device__ float g_wr_fc1[DMODEL * FFDIM];
__device__ float g_wr_fc2[FFDIM * DMODEL];

// ---------------- helpers ----------------
__device__ __forceinline__ uint32_t smem_u32(const void* p) {
    uint32_t a;
    asm("{ .reg .u64 t; cvta.to.shared.u64 t, %1; cvt.u32.u64 %0, t; }"
        : "=r"(a) : "l"(p));
    return a;
}

__device__ __forceinline__ float tf32r(float x) {
    uint32_t u;
    asm("cvt.rna.tf32.f32 %0, %1;" : "=r"(u) : "f"(x));
    return __uint_as_float(u);
}

#define CP_ASYNC16(dst, src) \
    asm volatile("cp.async.cg.shared.global [%0], [%1], 16;" :: "r"(dst), "l"(src) : "memory")
#define CP_COMMIT() asm volatile("cp.async.commit_group;" ::: "memory")
#define CP_WAIT2()  asm volatile("cp.async.wait_group 2;" ::: "memory")
#define CP_WAIT0()  asm volatile("cp.async.wait_group 0;" ::: "memory")

__device__ __forceinline__ void mma_tf32(float* c, const uint32_t* a, const uint32_t* b) {
    asm volatile(
        "mma.sync.aligned.m16n8k8.row.col.f32.tf32.tf32.f32 "
        "{%0,%1,%2,%3}, {%4,%5,%6,%7}, {%8,%9}, {%0,%1,%2,%3};"
        : "+f"(c[0]), "+f"(c[1]), "+f"(c[2]), "+f"(c[3])
        : "r"(a[0]), "r"(a[1]), "r"(a[2]), "r"(a[3]), "r"(b[0]), "r"(b[1]));
}

// ---------------- weight rounding (RNA tf32, elementwise) ----------------
__global__ __launch_bounds__(256) void round_tf32_kernel(
    const float* __restrict__ in, float* __restrict__ out, int n4)
{
    int i = blockIdx.x * 256 + threadIdx.x;
    if (i >= n4) return;
    float4 v = ((const float4*)in)[i];
    v.x = tf32r(v.x); v.y = tf32r(v.y); v.z = tf32r(v.z); v.w = tf32r(v.w);
    ((float4*)out)[i] = v;
}

// ---------------- tf32 mma.sync GEMM: C = A[M,K] @ B[K,N] + bias ----------
// BM=128, BN=128, BK=32, 4 stages, 256 threads (8 warps, 2x4), warp tile 64x32.
#define ASTR 36           // A smem row stride in floats (144 B)
#define BSTR 136          // B smem row stride in floats (544 B)
#define A_BYTES (128 * ASTR * 4)     // 18432
#define B_BYTES (32 * BSTR * 4)      // 17408
#define STG_BYTES (A_BYTES + B_BYTES)  // 35840
#define NSTAGE 4

template <int ACT, int RES, int ROUND>
__global__ __launch_bounds__(256, 1)
void gemm_mma(const float* __restrict__ A, const float* __restrict__ B,
              const float* __restrict__ bias, const float* __restrict__ res,
              float* __restrict__ C, int M, int N, int K)
{
    extern __shared__ __align__(16) char smem[];
    const uint32_t sb = smem_u32(smem);
    const int tid = threadIdx.x;
    const int wid = tid >> 5, lane = tid & 31;
    const int g = lane >> 2, t = lane & 3;
    const int warp_m = (wid >> 2) * 64;
    const int warp_n = (wid & 3) * 32;
    const int m0 = blockIdx.y * 128;
    const int n0 = blockIdx.x * 128;
    const int nk = K / 32;

    float c[4][4][4];
#pragma unroll
    for (int mt = 0; mt < 4; mt++)
#pragma unroll
        for (int nt = 0; nt < 4; nt++)
#pragma unroll
            for (int i = 0; i < 4; i++) c[mt][nt][i] = 0.f;

    auto load_tile = [&](int stage, int k0) {
        uint32_t sA = sb + (uint32_t)stage * STG_BYTES;
        uint32_t sB = sA + A_BYTES;
#pragma unroll
        for (int cc = 0; cc < 4; cc++) {
            int idx = tid + cc * 256;
            int row = idx >> 3, off = idx & 7;
            CP_ASYNC16(sA + (uint32_t)row * 144 + (uint32_t)off * 16,
                       (const char*)(A + (size_t)(m0 + row) * K + k0 + off * 4));
        }
#pragma unroll
        for (int cc = 0; cc < 4; cc++) {
            int idx = tid + cc * 256;
            int row = idx >> 5, off = idx & 31;
            CP_ASYNC16(sB + (uint32_t)row * 544 + (uint32_t)off * 16,
                       (const char*)(B + (size_t)(k0 + row) * N + n0 + off * 4));
        }
    };

    int k0 = 0;
#pragma unroll
    for (int s = 0; s < NSTAGE - 1; s++) {
        load_tile(s, k0);
        CP_COMMIT();
        k0 += 32;
    }

    for (int it = 0; it < nk; it++) {
        CP_WAIT2();
        __syncthreads();
        const int cur = it & (NSTAGE - 1);
        if (k0 < K) {
            load_tile((it + NSTAGE - 1) & (NSTAGE - 1), k0);
            k0 += 32;
        }
        CP_COMMIT();

        const float* As = (const float*)(smem + (size_t)cur * STG_BYTES);
        const float* Bs = (const float*)(smem + (size_t)cur * STG_BYTES + A_BYTES);

#pragma unroll
        for (int kk8 = 0; kk8 < 4; kk8++) {
            const int kk = kk8 * 8;
            uint32_t a[4][4], b[4][2];
#pragma unroll
            for (int mt = 0; mt < 4; mt++) {
                const float* ap = As + (warp_m + mt * 16 + g) * ASTR + kk + t;
                a[mt][0] = __float_as_uint(ap[0]);
                a[mt][2] = __float_as_uint(ap[4]);
                a[mt][1] = __float_as_uint(ap[8 * ASTR]);
                a[mt][3] = __float_as_uint(ap[8 * ASTR + 4]);
            }
#pragma unroll
            for (int nt = 0; nt < 4; nt++) {
                const float* bp = Bs + (kk + t) * BSTR + warp_n + nt * 8 + g;
                b[nt][0] = __float_as_uint(bp[0]);
                b[nt][1] = __float_as_uint(bp[4 * BSTR]);
            }
#pragma unroll
            for (int mt = 0; mt < 4; mt++)
#pragma unroll
                for (int nt = 0; nt < 4; nt++)
                    mma_tf32(c[mt][nt], a[mt], b[nt]);
        }
    }

#pragma unroll
    for (int mt = 0; mt < 4; mt++) {
        const int rm = m0 + warp_m + mt * 16 + g;
#pragma unroll
        for (int nt = 0; nt < 4; nt++) {
            const int cn = n0 + warp_n + nt * 8 + 2 * t;
            float2 bv = *(const float2*)(bias + cn);
            float v0 = c[mt][nt][0] + bv.x;
            float v1 = c[mt][nt][1] + bv.y;
            float v2 = c[mt][nt][2] + bv.x;
            float v3 = c[mt][nt][3] + bv.y;
            if (RES) {
                float2 r0 = *(const float2*)(res + (size_t)rm * N + cn);
                float2 r1 = *(const float2*)(res + (size_t)(rm + 8) * N + cn);
                v0 += r0.x; v1 += r0.y; v2 += r1.x; v3 += r1.y;
            }
            if (ACT) {
                v0 = v0 / (1.f + __expf(-1.702f * v0));
                v1 = v1 / (1.f + __expf(-1.702f * v1));
                v2 = v2 / (1.f + __expf(-1.702f * v2));
                v3 = v3 / (1.f + __expf(-1.702f * v3));
            }
            if (ROUND) {
                v0 = tf32r(v0); v1 = tf32r(v1); v2 = tf32r(v2); v3 = tf32r(v3);
            }
            *(float2*)(C + (size_t)rm * N + cn)       = make_float2(v0, v1);
            *(float2*)(C + (size_t)(rm + 8) * N + cn) = make_float2(v2, v3);
        }
    }
}

// ---------------- LayerNorm (tf32-rounded output) ----------------
__global__ __launch_bounds__(256) void ln_kernel(
    const float* __restrict__ x, const float* __restrict__ sc,
    const float* __restrict__ bi, float* __restrict__ out)
{
    int row = blockIdx.x;
    const float* xr = x + row * DMODEL;
    float* orow = out + row * DMODEL;
    int t = threadIdx.x;
    float v[5];
    float s = 0.f, s2 = 0.f;
#pragma unroll
    for (int i = 0; i < 5; i++) {
        v[i] = xr[t + i * 256];
        s += v[i];
        s2 = fmaf(v[i], v[i], s2);
    }
    __shared__ float rs[8], rs2[8];
#pragma unroll
    for (int o = 16; o; o >>= 1) {
        s  += __shfl_xor_sync(0xffffffffu, s, o);
        s2 += __shfl_xor_sync(0xffffffffu, s2, o);
    }
    if ((t & 31) == 0) { rs[t >> 5] = s; rs2[t >> 5] = s2; }
    __syncthreads();
    if (t < 32) {
        float a = (t < 8) ? rs[t] : 0.f;
        float b = (t < 8) ? rs2[t] : 0.f;
#pragma unroll
        for (int o = 4; o; o >>= 1) {
            a += __shfl_xor_sync(0xffffffffu, a, o);
            b += __shfl_xor_sync(0xffffffffu, b, o);
        }
        if (t == 0) { rs[0] = a; rs2[0] = b; }
    }
    __syncthreads();
    float mu = rs[0] * (1.f / DMODEL);
    float var = rs2[0] * (1.f / DMODEL) - mu * mu;
    float inv = rsqrtf(var + 1e-6f);
#pragma unroll
    for (int i = 0; i < 5; i++) {
        int c = t + i * 256;
        orow[c] = tf32r((v[i] - mu) * inv * sc[c] + bi[c]);
    }
}

// ---------------- RoPE on q and k in-place (tf32-rounded) ----------------
__global__ __launch_bounds__(256) void rope_kernel(
    float* __restrict__ qkv, const float* __restrict__ rot)
{
    int idx = blockIdx.x * 256 + threadIdx.x;
    const int total = S_LEN * 2 * NHEAD * 40;
    if (idx >= total) return;
    int i = idx % 40;
    int h = (idx / 40) % NHEAD;
    int w = (idx / (40 * NHEAD)) % 2;
    int s = idx / (40 * NHEAD * 2);
    float* p = qkv + (size_t)s * (3 * DMODEL) + w * DMODEL + h * HDIM;
    float x1 = p[i];
    float x2 = p[i + 40];
    float f1 = rot[s * 40 + (i >> 1)];
    float f2 = rot[s * 40 + 20 + (i >> 1)];
    float c1, s1, c2, s2v;
    sincosf(f1, &s1, &c1);
    sincosf(f2, &s2v, &c2);
    p[i]      = tf32r(x1 * c1 - x2 * s1);
    p[i + 40] = tf32r(x2 * c2 + x1 * s2v);
}

// ---------------- Flash attention with tf32 mma (block-diag segments) -----
// Block: 64 queries x 1 head, 128 threads (4 warps x 16 q-rows each).
// K-tiles of 64 keys, 2-stage cp.async double buffering, online softmax.
#define QKSTR 84   // Q/K smem row stride (floats); conflict-free frag loads
#define VSTRD 88   // V smem row stride
#define PSTRD 68   // P smem row stride
// smem float offsets
#define OFF_QP 0
#define OFF_K0 5376
#define OFF_K1 10752
#define OFF_V0 16128
#define OFF_V1 21760
#define ATTN_SMEM_FLOATS 27392

__global__ __launch_bounds__(128, 1) void attn_mma_kernel(
    const float* __restrict__ qkv, const int* __restrict__ cu,
    int nseg, float* __restrict__ out)
{
    extern __shared__ __align__(16) float sm[];
    const uint32_t sb = smem_u32(sm);
    const int tid = threadIdx.x;
    const int warp = tid >> 5, lane = tid & 31;
    const int g = lane >> 2, t = lane & 3;
    const int h = blockIdx.y;
    const int q0 = blockIdx.x * 64;
    const int w16 = warp * 16;

    int start = 0, end = S_LEN;
    for (int i = 0; i < nseg; i++) {
        int a = cu[i], b = cu[i + 1];
        if (q0 >= a && q0 < b) { start = a; end = b; break; }
    }
    const int L = end - start;
    const int ntiles = (L + 63) >> 6;

    // ---- stage Q into smem, then pull fragments to registers ----
    for (int i = tid; i < 64 * 20; i += 128) {
        int row = i / 20, c = i % 20;
        *(float4*)(sm + OFF_QP + row * QKSTR + c * 4) =
            *(const float4*)(qkv + (size_t)(q0 + row) * (3 * DMODEL) + h * HDIM + c * 4);
    }
    __syncthreads();
    uint32_t qf[10][4];
#pragma unroll
    for (int ks = 0; ks < 10; ks++) {
        const float* qp = sm + OFF_QP + (w16 + g) * QKSTR + ks * 8 + t;
        qf[ks][0] = __float_as_uint(qp[0]);
        qf[ks][2] = __float_as_uint(qp[4]);
        qf[ks][1] = __float_as_uint(qp[8 * QKSTR]);
        qf[ks][3] = __float_as_uint(qp[8 * QKSTR + 4]);
    }

    // ---- K/V tile prefetch (cp.async), OOB rows clamped (masked later) ----
    auto load_kv = [&](int stage, int k0) {
        const uint32_t kBase = sb + (stage ? OFF_K1 : OFF_K0) * 4;
        const uint32_t vBase = sb + (stage ? OFF_V1 : OFF_V0) * 4;
        for (int i = tid; i < 64 * 20; i += 128) {
            int row = i / 20, c = i % 20;
            int key = k0 + row;
            int src = start + (key < L ? key : L - 1);
            const char* kg = (const char*)(qkv + (size_t)src * (3 * DMODEL) + DMODEL + h * HDIM + c * 4);
            const char* vg = (const char*)(qkv + (size_t)src * (3 * DMODEL) + 2 * DMODEL + h * HDIM + c * 4);
            CP_ASYNC16(kBase + ((uint32_t)row * QKSTR + (uint32_t)c * 4) * 4, kg);
            CP_ASYNC16(vBase + ((uint32_t)row * VSTRD + (uint32_t)c * 4) * 4, vg);
        }
    };

    load_kv(0, 0);
    CP_COMMIT();

    const float scale = 0.111803398875f;   // 1/sqrt(80)
    float m[2] = {-1e30f, -1e30f};
    float l[2] = {0.f, 0.f};
    float o[10][4];
#pragma unroll
    for (int nt = 0; nt < 10; nt++)
#pragma unroll
        for (int i = 0; i < 4; i++) o[nt][i] = 0.f;

    float* P = sm + OFF_QP;   // reuse Q staging buffer (per-warp disjoint rows)

    for (int kt = 0; kt < ntiles; kt++) {
        CP_WAIT0();
        __syncthreads();
        if (kt + 1 < ntiles) {
            load_kv((kt + 1) & 1, (kt + 1) * 64);
            CP_COMMIT();
        }
        const float* K = sm + ((kt & 1) ? OFF_K1 : OFF_K0);
        const float* V = sm + ((kt & 1) ? OFF_V1 : OFF_V0);

        // ---- S = Q K^T ----
        float s[8][4];
#pragma unroll
        for (int nt = 0; nt < 8; nt++)
#pragma unroll
            for (int i = 0; i < 4; i++) s[nt][i] = 0.f;
#pragma unroll
        for (int ks = 0; ks < 10; ks++) {
            uint32_t b[8][2];
#pragma unroll
            for (int nt = 0; nt < 8; nt++) {
                const float* kp = K + (nt * 8 + g) * QKSTR + ks * 8 + t;
                b[nt][0] = __float_as_uint(kp[0]);
                b[nt][1] = __float_as_uint(kp[4]);
            }
#pragma unroll
            for (int nt = 0; nt < 8; nt++)
                mma_tf32(s[nt], qf[ks], b[nt]);
        }

        // ---- online softmax (per-warp rows; row spread over 4 lanes) ----
        const bool maskT = (kt == ntiles - 1) && (L & 63);
#pragma unroll
        for (int r = 0; r < 2; r++) {
            float mx = -1e30f;
#pragma unroll
            for (int nt = 0; nt < 8; nt++) {
                float v0 = s[nt][2 * r]     * scale;
                float v1 = s[nt][2 * r + 1] * scale;
                if (maskT) {
                    int col = kt * 64 + nt * 8 + 2 * t;
                    if (col >= L)     v0 = -1e30f;
                    if (col + 1 >= L) v1 = -1e30f;
                }
                s[nt][2 * r] = v0; s[nt][2 * r + 1] = v1;
                mx = fmaxf(mx, fmaxf(v0, v1));
            }
            mx = fmaxf(mx, __shfl_xor_sync(0xffffffffu, mx, 1));
            mx = fmaxf(mx, __shfl_xor_sync(0xffffffffu, mx, 2));
            float nm = fmaxf(m[r], mx);
            float fac = __expf(m[r] - nm);
            m[r] = nm;
            float sum = 0.f;
#pragma unroll
            for (int nt = 0; nt < 8; nt++) {
                float e0 = __expf(s[nt][2 * r] - nm);
                float e1 = __expf(s[nt][2 * r + 1] - nm);
                sum += e0 + e1;
                *(float2*)(P + (w16 + g + 8 * r) * PSTRD + nt * 8 + 2 * t) =
                    make_float2(e0, e1);
            }
            sum += __shfl_xor_sync(0xffffffffu, sum, 1);
            sum += __shfl_xor_sync(0xffffffffu, sum, 2);
            l[r] = l[r] * fac + sum;
#pragma unroll
            for (int nt = 0; nt < 10; nt++) {
                o[nt][2 * r] *= fac;
                o[nt][2 * r + 1] *= fac;
            }
        }
        __syncwarp();

        // ---- O += P V ----
#pragma unroll
        for (int ks = 0; ks < 8; ks++) {
            uint32_t a[4];
            const float* pp = P + (w16 + g) * PSTRD + ks * 8 + t;
            a[0] = __float_as_uint(pp[0]);
            a[2] = __float_as_uint(pp[4]);
            a[1] = __float_as_uint(pp[8 * PSTRD]);
            a[3] = __float_as_uint(pp[8 * PSTRD + 4]);
            uint32_t b[10][2];
#pragma unroll
            for (int nt = 0; nt < 10; nt++) {
                const float* vp = V + (ks * 8 + t) * VSTRD + nt * 8 + g;
                b[nt][0] = __float_as_uint(vp[0]);
                b[nt][1] = __float_as_uint(vp[4 * VSTRD]);
            }
#pragma unroll
            for (int nt = 0; nt < 10; nt++)
                mma_tf32(o[nt], a, b[nt]);
        }
        __syncwarp();
    }

    // ---- epilogue: normalize, round, store ----
#pragma unroll
    for (int r = 0; r < 2; r++) {
        float inv = 1.f / l[r];
        const int row = q0 + w16 + g + 8 * r;
#pragma unroll
        for (int nt = 0; nt < 10; nt++) {
            float v0 = tf32r(o[nt][2 * r] * inv);
            float v1 = tf32r(o[nt][2 * r + 1] * inv);
            *(float2*)(out + (size_t)row * DMODEL + h * HDIM + nt * 8 + 2 * t) =
                make_float2(v0, v1);
        }
    }
}

// ---------------- launch ----------------
static float* sym_addr_f(const void* sym)
{
    void* p = nullptr;
    cudaGetSymbolAddress(&p, sym);
    return (float*)p;
}

extern "C" void kernel_launch(void* const* d_in, const int* in_sizes, int n_in,
                              void* d_out, int out_size)
{
    const float* x        = (const float*)d_in[0];
    const float* rot      = (const float*)d_in[1];
    const float* ln1_s    = (const float*)d_in[2];
    const float* ln1_b    = (const float*)d_in[3];
    const float* ln2_s    = (const float*)d_in[4];
    const float* ln2_b    = (const float*)d_in[5];
    const float* qkv_w    = (const float*)d_in[6];
    const float* qkv_b    = (const float*)d_in[7];
    const float* proj_w   = (const float*)d_in[8];
    const float* proj_b   = (const float*)d_in[9];
    const float* fc1_w    = (const float*)d_in[10];
    const float* fc1_b    = (const float*)d_in[11];
    const float* fc2_w    = (const float*)d_in[12];
    const float* fc2_b    = (const float*)d_in[13];
    const int*   cu       = (const int*)d_in[14];
    float*       out      = (float*)d_out;
    const int    nseg     = in_sizes[14] - 1;

    float* h     = sym_addr_f(g_h);
    float* qkv   = sym_addr_f(g_qkv);
    float* attn  = sym_addr_f(g_attn);
    float* x1    = sym_addr_f(g_x1);
    float* ff    = sym_addr_f(g_ff);
    float* wqkv  = sym_addr_f(g_wr_qkv);
    float* wproj = sym_addr_f(g_wr_proj);
    float* wfc1  = sym_addr_f(g_wr_fc1);
    float* wfc2  = sym_addr_f(g_wr_fc2);

    const int attn_smem = ATTN_SMEM_FLOATS * (int)sizeof(float);   // 109568
    cudaFuncSetAttribute(attn_mma_kernel, cudaFuncAttributeMaxDynamicSharedMemorySize, attn_smem);
    const int gemm_smem = NSTAGE * STG_BYTES;  // 143360
    cudaFuncSetAttribute(gemm_mma<0, 0, 1>, cudaFuncAttributeMaxDynamicSharedMemorySize, gemm_smem);
    cudaFuncSetAttribute(gemm_mma<0, 1, 0>, cudaFuncAttributeMaxDynamicSharedMemorySize, gemm_smem);
    cudaFuncSetAttribute(gemm_mma<1, 0, 1>, cudaFuncAttributeMaxDynamicSharedMemorySize, gemm_smem);

    // 0) weight rounding to tf32 (RNA)
    {
        int n;
        n = DMODEL * 3 * DMODEL / 4;
        round_tf32_kernel<<<(n + 255) / 256, 256>>>(qkv_w, wqkv, n);
        n = DMODEL * DMODEL / 4;
        round_tf32_kernel<<<(n + 255) / 256, 256>>>(proj_w, wproj, n);
        n = DMODEL * FFDIM / 4;
        round_tf32_kernel<<<(n + 255) / 256, 256>>>(fc1_w, wfc1, n);
        n = FFDIM * DMODEL / 4;
        round_tf32_kernel<<<(n + 255) / 256, 256>>>(fc2_w, wfc2, n);
    }

    // 1) LN1 (tf32-rounded)
    ln_kernel<<<S_LEN, 256>>>(x, ln1_s, ln1_b, h);
    // 2) QKV = h @ qkv_w + b  (tf32-rounded output for attention)
    gemm_mma<0, 0, 1><<<dim3(3 * DMODEL / 128, S_LEN / 128), 256, gemm_smem>>>(
        h, wqkv, qkv_b, nullptr, qkv, S_LEN, 3 * DMODEL, DMODEL);
    // 3) RoPE (rounds q,k)
    {
        int total = S_LEN * 2 * NHEAD * 40;
        rope_kernel<<<(total + 255) / 256, 256>>>(qkv, rot);
    }
    // 4) flash attention (tensor cores)
    attn_mma_kernel<<<dim3(S_LEN / 64, NHEAD), 128, attn_smem>>>(qkv, cu, nseg, attn);
    // 5) x1 = x + attn @ proj_w + proj_b
    gemm_mma<0, 1, 0><<<dim3(DMODEL / 128, S_LEN / 128), 256, gemm_smem>>>(
        attn, wproj, proj_b, x, x1, S_LEN, DMODEL, DMODEL);
    // 6) LN2
    ln_kernel<<<S_LEN, 256>>>(x1, ln2_s, ln2_b, h);
    // 7) ff = quick_gelu(h @ fc1_w + fc1_b)  (tf32-rounded)
    gemm_mma<1, 0, 1><<<dim3(FFDIM / 128, S_LEN / 128), 256, gemm_smem>>>(
        h, wfc1, fc1_b, nullptr, ff, S_LEN, FFDIM, DMODEL);
    // 8) out = x1 + ff @ fc2_w + fc2_b
    gemm_mma<0, 1, 0><<<dim3(DMODEL / 128, S_LEN / 128), 256, gemm_smem>>>(
        ff, wfc2, fc2_b, x1, out, S_LEN, DMODEL, FFDIM);
}

// round 10
// speedup vs baseline: 4.8164x; 1.0409x over previous
#include <cuda_runtime.h>
#include <cuda_bf16.h>
#include <math.h>
#include <stdint.h>

#define S_LEN 3072
#define DMODEL 1280
#define NHEAD 16
#define HDIM 80
#define FFDIM 5120

// ---------------- scratch (device globals; no allocations allowed) ----------
__device__ float g_h[S_LEN * DMODEL];          // LN output (tf32-rounded)
__device__ float g_qkv[S_LEN * 3 * DMODEL];    // QKV (tf32-rounded)
__device__ float g_attn[S_LEN * DMODEL];       // attention output (tf32-rounded)
__device__ float g_x1[S_LEN * DMODEL];         // x + proj(attn)
__device__ float g_ff[S_LEN * FFDIM];          // gelu(fc1) (tf32-rounded)
__device__ float g_wr_qkv[DMODEL * 3 * DMODEL];   // rounded weights [K,N]
__device__ float g_wr_proj[DMODEL * DMODEL];
__device__ float g_wr_fc1[DMODEL * FFDIM];
__device__ float g_wr_fc2[FFDIM * DMODEL];

// ---------------- helpers ----------------
__device__ __forceinline__ uint32_t smem_u32(const void* p) {
    uint32_t a;
    asm("{ .reg .u64 t; cvta.to.shared.u64 t, %1; cvt.u32.u64 %0, t; }"
        : "=r"(a) : "l"(p));
    return a;
}

__device__ __forceinline__ float tf32r(float x) {
    uint32_t u;
    asm("cvt.rna.tf32.f32 %0, %1;" : "=r"(u) : "f"(x));
    return __uint_as_float(u);
}

#define CP_ASYNC16(dst, src) \
    asm volatile("cp.async.cg.shared.global [%0], [%1], 16;" :: "r"(dst), "l"(src) : "memory")
#define CP_COMMIT() asm volatile("cp.async.commit_group;" ::: "memory")
#define CP_WAIT2()  asm volatile("cp.async.wait_group 2;" ::: "memory")
#define CP_WAIT0()  asm volatile("cp.async.wait_group 0;" ::: "memory")

__device__ __forceinline__ void mma_tf32(float* c, const uint32_t* a, const uint32_t* b) {
    asm volatile(
        "mma.sync.aligned.m16n8k8.row.col.f32.tf32.tf32.f32 "
        "{%0,%1,%2,%3}, {%4,%5,%6,%7}, {%8,%9}, {%0,%1,%2,%3};"
        : "+f"(c[0]), "+f"(c[1]), "+f"(c[2]), "+f"(c[3])
        : "r"(a[0]), "r"(a[1]), "r"(a[2]), "r"(a[3]), "r"(b[0]), "r"(b[1]));
}

// ---------------- weight rounding (RNA tf32, elementwise) ----------------
__global__ __launch_bounds__(256) void round_tf32_kernel(
    const float* __restrict__ in, float* __restrict__ out, int n4)
{
    int i = blockIdx.x * 256 + threadIdx.x;
    if (i >= n4) return;
    float4 v = ((const float4*)in)[i];
    v.x = tf32r(v.x); v.y = tf32r(v.y); v.z = tf32r(v.z); v.w = tf32r(v.w);
    ((float4*)out)[i] = v;
}

// ---------------- tf32 mma.sync GEMM: C = A[M,K] @ B[K,N] + bias ----------
// BM=128, BN=256, BK=32, 4 stages, 256 threads (8 warps 2x4), warp tile 64x64.
#define ASTR 36           // A smem row stride in floats (144 B)
#define BSTR 264          // B smem row stride in floats (1056 B); 264%32=8 -> banks 8t+g
#define A_BYTES (128 * ASTR * 4)       // 18432
#define B_BYTES (32 * BSTR * 4)        // 33792
#define STG_BYTES (A_BYTES + B_BYTES)  // 52224
#define NSTAGE 4

template <int ACT, int RES, int ROUND>
__global__ __launch_bounds__(256, 1)
void gemm_mma(const float* __restrict__ A, const float* __restrict__ B,
              const float* __restrict__ bias, const float* __restrict__ res,
              float* __restrict__ C, int M, int N, int K)
{
    extern __shared__ __align__(16) char smem[];
    const uint32_t sb = smem_u32(smem);
    const int tid = threadIdx.x;
    const int wid = tid >> 5, lane = tid & 31;
    const int g = lane >> 2, t = lane & 3;
    const int warp_m = (wid >> 2) * 64;   // 0 or 64
    const int warp_n = (wid & 3) * 64;    // 0,64,128,192
    const int m0 = blockIdx.y * 128;
    const int n0 = blockIdx.x * 256;
    const int nk = K / 32;

    float c[4][8][4];
#pragma unroll
    for (int mt = 0; mt < 4; mt++)
#pragma unroll
        for (int nt = 0; nt < 8; nt++)
#pragma unroll
            for (int i = 0; i < 4; i++) c[mt][nt][i] = 0.f;

    auto load_tile = [&](int stage, int k0) {
        uint32_t sA = sb + (uint32_t)stage * STG_BYTES;
        uint32_t sB = sA + A_BYTES;
#pragma unroll
        for (int cc = 0; cc < 4; cc++) {             // A: 128 rows x 8 chunks
            int idx = tid + cc * 256;
            int row = idx >> 3, off = idx & 7;
            CP_ASYNC16(sA + (uint32_t)row * 144 + (uint32_t)off * 16,
                       (const char*)(A + (size_t)(m0 + row) * K + k0 + off * 4));
        }
#pragma unroll
        for (int cc = 0; cc < 8; cc++) {             // B: 32 rows x 64 chunks
            int idx = tid + cc * 256;
            int row = idx >> 6, off = idx & 63;
            CP_ASYNC16(sB + (uint32_t)row * 1056 + (uint32_t)off * 16,
                       (const char*)(B + (size_t)(k0 + row) * N + n0 + off * 4));
        }
    };

    int k0 = 0;
#pragma unroll
    for (int s = 0; s < NSTAGE - 1; s++) {
        load_tile(s, k0);
        CP_COMMIT();
        k0 += 32;
    }

    for (int it = 0; it < nk; it++) {
        CP_WAIT2();
        __syncthreads();
        const int cur = it & (NSTAGE - 1);
        if (k0 < K) {
            load_tile((it + NSTAGE - 1) & (NSTAGE - 1), k0);
            k0 += 32;
        }
        CP_COMMIT();

        const float* As = (const float*)(smem + (size_t)cur * STG_BYTES);
        const float* Bs = (const float*)(smem + (size_t)cur * STG_BYTES + A_BYTES);

#pragma unroll
        for (int kk8 = 0; kk8 < 4; kk8++) {
            const int kk = kk8 * 8;
            uint32_t a[4][4], b[8][2];
#pragma unroll
            for (int mt = 0; mt < 4; mt++) {
                const float* ap = As + (warp_m + mt * 16 + g) * ASTR + kk + t;
                a[mt][0] = __float_as_uint(ap[0]);
                a[mt][2] = __float_as_uint(ap[4]);
                a[mt][1] = __float_as_uint(ap[8 * ASTR]);
                a[mt][3] = __float_as_uint(ap[8 * ASTR + 4]);
            }
#pragma unroll
            for (int nt = 0; nt < 8; nt++) {
                const float* bp = Bs + (kk + t) * BSTR + warp_n + nt * 8 + g;
                b[nt][0] = __float_as_uint(bp[0]);
                b[nt][1] = __float_as_uint(bp[4 * BSTR]);
            }
#pragma unroll
            for (int mt = 0; mt < 4; mt++)
#pragma unroll
                for (int nt = 0; nt < 8; nt++)
                    mma_tf32(c[mt][nt], a[mt], b[nt]);
        }
    }

#pragma unroll
    for (int mt = 0; mt < 4; mt++) {
        const int rm = m0 + warp_m + mt * 16 + g;
#pragma unroll
        for (int nt = 0; nt < 8; nt++) {
            const int cn = n0 + warp_n + nt * 8 + 2 * t;
            float2 bv = *(const float2*)(bias + cn);
            float v0 = c[mt][nt][0] + bv.x;
            float v1 = c[mt][nt][1] + bv.y;
            float v2 = c[mt][nt][2] + bv.x;
            float v3 = c[mt][nt][3] + bv.y;
            if (RES) {
                float2 r0 = *(const float2*)(res + (size_t)rm * N + cn);
                float2 r1 = *(const float2*)(res + (size_t)(rm + 8) * N + cn);
                v0 += r0.x; v1 += r0.y; v2 += r1.x; v3 += r1.y;
            }
            if (ACT) {
                v0 = v0 / (1.f + __expf(-1.702f * v0));
                v1 = v1 / (1.f + __expf(-1.702f * v1));
                v2 = v2 / (1.f + __expf(-1.702f * v2));
                v3 = v3 / (1.f + __expf(-1.702f * v3));
            }
            if (ROUND) {
                v0 = tf32r(v0); v1 = tf32r(v1); v2 = tf32r(v2); v3 = tf32r(v3);
            }
            *(float2*)(C + (size_t)rm * N + cn)       = make_float2(v0, v1);
            *(float2*)(C + (size_t)(rm + 8) * N + cn) = make_float2(v2, v3);
        }
    }
}

// ---------------- LayerNorm (tf32-rounded output) ----------------
__global__ __launch_bounds__(256) void ln_kernel(
    const float* __restrict__ x, const float* __restrict__ sc,
    const float* __restrict__ bi, float* __restrict__ out)
{
    int row = blockIdx.x;
    const float* xr = x + row * DMODEL;
    float* orow = out + row * DMODEL;
    int t = threadIdx.x;
    float v[5];
    float s = 0.f, s2 = 0.f;
#pragma unroll
    for (int i = 0; i < 5; i++) {
        v[i] = xr[t + i * 256];
        s += v[i];
        s2 = fmaf(v[i], v[i], s2);
    }
    __shared__ float rs[8], rs2[8];
#pragma unroll
    for (int o = 16; o; o >>= 1) {
        s  += __shfl_xor_sync(0xffffffffu, s, o);
        s2 += __shfl_xor_sync(0xffffffffu, s2, o);
    }
    if ((t & 31) == 0) { rs[t >> 5] = s; rs2[t >> 5] = s2; }
    __syncthreads();
    if (t < 32) {
        float a = (t < 8) ? rs[t] : 0.f;
        float b = (t < 8) ? rs2[t] : 0.f;
#pragma unroll
        for (int o = 4; o; o >>= 1) {
            a += __shfl_xor_sync(0xffffffffu, a, o);
            b += __shfl_xor_sync(0xffffffffu, b, o);
        }
        if (t == 0) { rs[0] = a; rs2[0] = b; }
    }
    __syncthreads();
    float mu = rs[0] * (1.f / DMODEL);
    float var = rs2[0] * (1.f / DMODEL) - mu * mu;
    float inv = rsqrtf(var + 1e-6f);
#pragma unroll
    for (int i = 0; i < 5; i++) {
        int c = t + i * 256;
        orow[c] = tf32r((v[i] - mu) * inv * sc[c] + bi[c]);
    }
}

// ---------------- RoPE on q and k in-place (tf32-rounded) ----------------
__global__ __launch_bounds__(256) void rope_kernel(
    float* __restrict__ qkv, const float* __restrict__ rot)
{
    int idx = blockIdx.x * 256 + threadIdx.x;
    const int total = S_LEN * 2 * NHEAD * 40;
    if (idx >= total) return;
    int i = idx % 40;
    int h = (idx / 40) % NHEAD;
    int w = (idx / (40 * NHEAD)) % 2;
    int s = idx / (40 * NHEAD * 2);
    float* p = qkv + (size_t)s * (3 * DMODEL) + w * DMODEL + h * HDIM;
    float x1 = p[i];
    float x2 = p[i + 40];
    float f1 = rot[s * 40 + (i >> 1)];
    float f2 = rot[s * 40 + 20 + (i >> 1)];
    float c1, s1, c2, s2v;
    sincosf(f1, &s1, &c1);
    sincosf(f2, &s2v, &c2);
    p[i]      = tf32r(x1 * c1 - x2 * s1);
    p[i + 40] = tf32r(x2 * c2 + x1 * s2v);
}

// ---------------- Flash attention with tf32 mma (block-diag segments) -----
// Block: 64 queries x 1 head, 128 threads (4 warps x 16 q-rows each).
// K-tiles of 64 keys, 2-stage cp.async double buffering, online softmax.
#define QKSTR 84   // Q/K smem row stride (floats); conflict-free frag loads
#define VSTRD 88   // V smem row stride
#define PSTRD 68   // P smem row stride
// smem float offsets
#define OFF_QP 0
#define OFF_K0 5376
#define OFF_K1 10752
#define OFF_V0 16128
#define OFF_V1 21760
#define ATTN_SMEM_FLOATS 27392

__global__ __launch_bounds__(128, 1) void attn_mma_kernel(
    const float* __restrict__ qkv, const int* __restrict__ cu,
    int nseg, float* __restrict__ out)
{
    extern __shared__ __align__(16) float sm[];
    const uint32_t sb = smem_u32(sm);
    const int tid = threadIdx.x;
    const int warp = tid >> 5, lane = tid & 31;
    const int g = lane >> 2, t = lane & 3;
    const int h = blockIdx.y;
    const int q0 = blockIdx.x * 64;
    const int w16 = warp * 16;

    int start = 0, end = S_LEN;
    for (int i = 0; i < nseg; i++) {
        int a = cu[i], b = cu[i + 1];
        if (q0 >= a && q0 < b) { start = a; end = b; break; }
    }
    const int L = end - start;
    const int ntiles = (L + 63) >> 6;

    // ---- stage Q into smem, then pull fragments to registers ----
    for (int i = tid; i < 64 * 20; i += 128) {
        int row = i / 20, c = i % 20;
        *(float4*)(sm + OFF_QP + row * QKSTR + c * 4) =
            *(const float4*)(qkv + (size_t)(q0 + row) * (3 * DMODEL) + h * HDIM + c * 4);
    }
    __syncthreads();
    uint32_t qf[10][4];
#pragma unroll
    for (int ks = 0; ks < 10; ks++) {
        const float* qp = sm + OFF_QP + (w16 + g) * QKSTR + ks * 8 + t;
        qf[ks][0] = __float_as_uint(qp[0]);
        qf[ks][2] = __float_as_uint(qp[4]);
        qf[ks][1] = __float_as_uint(qp[8 * QKSTR]);
        qf[ks][3] = __float_as_uint(qp[8 * QKSTR + 4]);
    }

    // ---- K/V tile prefetch (cp.async), OOB rows clamped (masked later) ----
    auto load_kv = [&](int stage, int k0) {
        const uint32_t kBase = sb + (stage ? OFF_K1 : OFF_K0) * 4;
        const uint32_t vBase = sb + (stage ? OFF_V1 : OFF_V0) * 4;
        for (int i = tid; i < 64 * 20; i += 128) {
            int row = i / 20, c = i % 20;
            int key = k0 + row;
            int src = start + (key < L ? key : L - 1);
            const char* kg = (const char*)(qkv + (size_t)src * (3 * DMODEL) + DMODEL + h * HDIM + c * 4);
            const char* vg = (const char*)(qkv + (size_t)src * (3 * DMODEL) + 2 * DMODEL + h * HDIM + c * 4);
            CP_ASYNC16(kBase + ((uint32_t)row * QKSTR + (uint32_t)c * 4) * 4, kg);
            CP_ASYNC16(vBase + ((uint32_t)row * VSTRD + (uint32_t)c * 4) * 4, vg);
        }
    };

    load_kv(0, 0);
    CP_COMMIT();

    const float scale = 0.111803398875f;   // 1/sqrt(80)
    float m[2] = {-1e30f, -1e30f};
    float l[2] = {0.f, 0.f};
    float o[10][4];
#pragma unroll
    for (int nt = 0; nt < 10; nt++)
#pragma unroll
        for (int i = 0; i < 4; i++) o[nt][i] = 0.f;

    float* P = sm + OFF_QP;   // reuse Q staging buffer (per-warp disjoint rows)

    for (int kt = 0; kt < ntiles; kt++) {
        CP_WAIT0();
        __syncthreads();
        if (kt + 1 < ntiles) {
            load_kv((kt + 1) & 1, (kt + 1) * 64);
            CP_COMMIT();
        }
        const float* K = sm + ((kt & 1) ? OFF_K1 : OFF_K0);
        const float* V = sm + ((kt & 1) ? OFF_V1 : OFF_V0);

        // ---- S = Q K^T ----
        float s[8][4];
#pragma unroll
        for (int nt = 0; nt < 8; nt++)
#pragma unroll
            for (int i = 0; i < 4; i++) s[nt][i] = 0.f;
#pragma unroll
        for (int ks = 0; ks < 10; ks++) {
            uint32_t b[8][2];
#pragma unroll
            for (int nt = 0; nt < 8; nt++) {
                const float* kp = K + (nt * 8 + g) * QKSTR + ks * 8 + t;
                b[nt][0] = __float_as_uint(kp[0]);
                b[nt][1] = __float_as_uint(kp[4]);
            }
#pragma unroll
            for (int nt = 0; nt < 8; nt++)
                mma_tf32(s[nt], qf[ks], b[nt]);
        }

        // ---- online softmax (per-warp rows; row spread over 4 lanes) ----
        const bool maskT = (kt == ntiles - 1) && (L & 63);
#pragma unroll
        for (int r = 0; r < 2; r++) {
            float mx = -1e30f;
#pragma unroll
            for (int nt = 0; nt < 8; nt++) {
                float v0 = s[nt][2 * r]     * scale;
                float v1 = s[nt][2 * r + 1] * scale;
                if (maskT) {
                    int col = kt * 64 + nt * 8 + 2 * t;
                    if (col >= L)     v0 = -1e30f;
                    if (col + 1 >= L) v1 = -1e30f;
                }
                s[nt][2 * r] = v0; s[nt][2 * r + 1] = v1;
                mx = fmaxf(mx, fmaxf(v0, v1));
            }
            mx = fmaxf(mx, __shfl_xor_sync(0xffffffffu, mx, 1));
            mx = fmaxf(mx, __shfl_xor_sync(0xffffffffu, mx, 2));
            float nm = fmaxf(m[r], mx);
            float fac = __expf(m[r] - nm);
            m[r] = nm;
            float sum = 0.f;
#pragma unroll
            for (int nt = 0; nt < 8; nt++) {
                float e0 = __expf(s[nt][2 * r] - nm);
                float e1 = __expf(s[nt][2 * r + 1] - nm);
                sum += e0 + e1;
                *(float2*)(P + (w16 + g + 8 * r) * PSTRD + nt * 8 + 2 * t) =
                    make_float2(e0, e1);
            }
            sum += __shfl_xor_sync(0xffffffffu, sum, 1);
            sum += __shfl_xor_sync(0xffffffffu, sum, 2);
            l[r] = l[r] * fac + sum;
#pragma unroll
            for (int nt = 0; nt < 10; nt++) {
                o[nt][2 * r] *= fac;
                o[nt][2 * r + 1] *= fac;
            }
        }
        __syncwarp();

        // ---- O += P V ----
#pragma unroll
        for (int ks = 0; ks < 8; ks++) {
            uint32_t a[4];
            const float* pp = P + (w16 + g) * PSTRD + ks * 8 + t;
            a[0] = __float_as_uint(pp[0]);
            a[2] = __float_as_uint(pp[4]);
            a[1] = __float_as_uint(pp[8 * PSTRD]);
            a[3] = __float_as_uint(pp[8 * PSTRD + 4]);
            uint32_t b[10][2];
#pragma unroll
            for (int nt = 0; nt < 10; nt++) {
                const float* vp = V + (ks * 8 + t) * VSTRD + nt * 8 + g;
                b[nt][0] = __float_as_uint(vp[0]);
                b[nt][1] = __float_as_uint(vp[4 * VSTRD]);
            }
#pragma unroll
            for (int nt = 0; nt < 10; nt++)
                mma_tf32(o[nt], a, b[nt]);
        }
        __syncwarp();
    }

    // ---- epilogue: normalize, round, store ----
#pragma unroll
    for (int r = 0; r < 2; r++) {
        float inv = 1.f / l[r];
        const int row = q0 + w16 + g + 8 * r;
#pragma unroll
        for (int nt = 0; nt < 10; nt++) {
            float v0 = tf32r(o[nt][2 * r] * inv);
            float v1 = tf32r(o[nt][2 * r + 1] * inv);
            *(float2*)(out + (size_t)row * DMODEL + h * HDIM + nt * 8 + 2 * t) =
                make_float2(v0, v1);
        }
    }
}

// ---------------- launch ----------------
static float* sym_addr_f(const void* sym)
{
    void* p = nullptr;
    cudaGetSymbolAddress(&p, sym);
    return (float*)p;
}

extern "C" void kernel_launch(void* const* d_in, const int* in_sizes, int n_in,
                              void* d_out, int out_size)
{
    const float* x        = (const float*)d_in[0];
    const float* rot      = (const float*)d_in[1];
    const float* ln1_s    = (const float*)d_in[2];
    const float* ln1_b    = (const float*)d_in[3];
    const float* ln2_s    = (const float*)d_in[4];
    const float* ln2_b    = (const float*)d_in[5];
    const float* qkv_w    = (const float*)d_in[6];
    const float* qkv_b    = (const float*)d_in[7];
    const float* proj_w   = (const float*)d_in[8];
    const float* proj_b   = (const float*)d_in[9];
    const float* fc1_w    = (const float*)d_in[10];
    const float* fc1_b    = (const float*)d_in[11];
    const float* fc2_w    = (const float*)d_in[12];
    const float* fc2_b    = (const float*)d_in[13];
    const int*   cu       = (const int*)d_in[14];
    float*       out      = (float*)d_out;
    const int    nseg     = in_sizes[14] - 1;

    float* h     = sym_addr_f(g_h);
    float* qkv   = sym_addr_f(g_qkv);
    float* attn  = sym_addr_f(g_attn);
    float* x1    = sym_addr_f(g_x1);
    float* ff    = sym_addr_f(g_ff);
    float* wqkv  = sym_addr_f(g_wr_qkv);
    float* wproj = sym_addr_f(g_wr_proj);
    float* wfc1  = sym_addr_f(g_wr_fc1);
    float* wfc2  = sym_addr_f(g_wr_fc2);

    const int attn_smem = ATTN_SMEM_FLOATS * (int)sizeof(float);   // 109568
    cudaFuncSetAttribute(attn_mma_kernel, cudaFuncAttributeMaxDynamicSharedMemorySize, attn_smem);
    const int gemm_smem = NSTAGE * STG_BYTES;  // 208896
    cudaFuncSetAttribute(gemm_mma<0, 0, 1>, cudaFuncAttributeMaxDynamicSharedMemorySize, gemm_smem);
    cudaFuncSetAttribute(gemm_mma<0, 1, 0>, cudaFuncAttributeMaxDynamicSharedMemorySize, gemm_smem);
    cudaFuncSetAttribute(gemm_mma<1, 0, 1>, cudaFuncAttributeMaxDynamicSharedMemorySize, gemm_smem);

    // 0) weight rounding to tf32 (RNA)
    {
        int n;
        n = DMODEL * 3 * DMODEL / 4;
        round_tf32_kernel<<<(n + 255) / 256, 256>>>(qkv_w, wqkv, n);
        n = DMODEL * DMODEL / 4;
        round_tf32_kernel<<<(n + 255) / 256, 256>>>(proj_w, wproj, n);
        n = DMODEL * FFDIM / 4;
        round_tf32_kernel<<<(n + 255) / 256, 256>>>(fc1_w, wfc1, n);
        n = FFDIM * DMODEL / 4;
        round_tf32_kernel<<<(n + 255) / 256, 256>>>(fc2_w, wfc2, n);
    }

    // 1) LN1 (tf32-rounded)
    ln_kernel<<<S_LEN, 256>>>(x, ln1_s, ln1_b, h);
    // 2) QKV = h @ qkv_w + b  (tf32-rounded output for attention)
    gemm_mma<0, 0, 1><<<dim3(3 * DMODEL / 256, S_LEN / 128), 256, gemm_smem>>>(
        h, wqkv, qkv_b, nullptr, qkv, S_LEN, 3 * DMODEL, DMODEL);
    // 3) RoPE (rounds q,k)
    {
        int total = S_LEN * 2 * NHEAD * 40;
        rope_kernel<<<(total + 255) / 256, 256>>>(qkv, rot);
    }
    // 4) flash attention (tensor cores)
    attn_mma_kernel<<<dim3(S_LEN / 64, NHEAD), 128, attn_smem>>>(qkv, cu, nseg, attn);
    // 5) x1 = x + attn @ proj_w + proj_b
    gemm_mma<0, 1, 0><<<dim3(DMODEL / 256, S_LEN / 128), 256, gemm_smem>>>(
        attn, wproj, proj_b, x, x1, S_LEN, DMODEL, DMODEL);
    // 6) LN2
    ln_kernel<<<S_LEN, 256>>>(x1, ln2_s, ln2_b, h);
    // 7) ff = quick_gelu(h @ fc1_w + fc1_b)  (tf32-rounded)
    gemm_mma<1, 0, 1><<<dim3(FFDIM / 256, S_LEN / 128), 256, gemm_smem>>>(
        h, wfc1, fc1_b, nullptr, ff, S_LEN, FFDIM, DMODEL);
    // 8) out = x1 + ff @ fc2_w + fc2_b
    gemm_mma<0, 1, 0><<<dim3(DMODEL / 256, S_LEN / 128), 256, gemm_smem>>>(
        ff, wfc2, fc2_b, x1, out, S_LEN, DMODEL, FFDIM);
}

// round 11
// speedup vs baseline: 6.8950x; 1.4316x over previous
#include <cuda_runtime.h>
#include <cuda_fp16.h>
#include <math.h>
#include <stdint.h>

#define S_LEN 3072
#define DMODEL 1280
#define NHEAD 16
#define HDIM 80
#define FFDIM 5120

// ---------------- scratch (device globals; no allocations allowed) ----------
__device__ __half g_hh[S_LEN * DMODEL];        // LN output (fp16)
__device__ float  g_qkv[S_LEN * 3 * DMODEL];   // QKV (fp32, tf32-rounded)
__device__ __half g_attnh[S_LEN * DMODEL];     // attention output (fp16)
__device__ float  g_x1[S_LEN * DMODEL];        // x + proj(attn)  (fp32)
__device__ __half g_ffh[S_LEN * FFDIM];        // gelu(fc1) (fp16)
__device__ __half g_wh_qkv[3 * DMODEL * DMODEL];  // weights [N][K] fp16
__device__ __half g_wh_proj[DMODEL * DMODEL];
__device__ __half g_wh_fc1[FFDIM * DMODEL];
__device__ __half g_wh_fc2[DMODEL * FFDIM];

// ---------------- helpers ----------------
__device__ __forceinline__ uint32_t smem_u32(const void* p) {
    uint32_t a;
    asm("{ .reg .u64 t; cvta.to.shared.u64 t, %1; cvt.u32.u64 %0, t; }"
        : "=r"(a) : "l"(p));
    return a;
}

__device__ __forceinline__ float tf32r(float x) {
    uint32_t u;
    asm("cvt.rna.tf32.f32 %0, %1;" : "=r"(u) : "f"(x));
    return __uint_as_float(u);
}

#define CP_ASYNC16(dst, src) \
    asm volatile("cp.async.cg.shared.global [%0], [%1], 16;" :: "r"(dst), "l"(src) : "memory")
#define CP_COMMIT() asm volatile("cp.async.commit_group;" ::: "memory")
#define CP_WAIT2()  asm volatile("cp.async.wait_group 2;" ::: "memory")
#define CP_WAIT0()  asm volatile("cp.async.wait_group 0;" ::: "memory")

// fp16 mma: D(f32) += A(f16 m16k16,row) * B(f16 k16n8,col)
__device__ __forceinline__ void mma_f16(float* c, const uint32_t* a, const uint32_t* b) {
    asm volatile(
        "mma.sync.aligned.m16n8k16.row.col.f32.f16.f16.f32 "
        "{%0,%1,%2,%3}, {%4,%5,%6,%7}, {%8,%9}, {%0,%1,%2,%3};"
        : "+f"(c[0]), "+f"(c[1]), "+f"(c[2]), "+f"(c[3])
        : "r"(a[0]), "r"(a[1]), "r"(a[2]), "r"(a[3]), "r"(b[0]), "r"(b[1]));
}

// tf32 mma (attention only)
__device__ __forceinline__ void mma_tf32(float* c, const uint32_t* a, const uint32_t* b) {
    asm volatile(
        "mma.sync.aligned.m16n8k8.row.col.f32.tf32.tf32.f32 "
        "{%0,%1,%2,%3}, {%4,%5,%6,%7}, {%8,%9}, {%0,%1,%2,%3};"
        : "+f"(c[0]), "+f"(c[1]), "+f"(c[2]), "+f"(c[3])
        : "r"(a[0]), "r"(a[1]), "r"(a[2]), "r"(a[3]), "r"(b[0]), "r"(b[1]));
}

// ---------------- weight transpose + fp16 convert: in[K,N] -> out[N,K] ----
__global__ __launch_bounds__(256) void transpose_h(
    const float* __restrict__ in, __half* __restrict__ out, int K, int N)
{
    __shared__ float t[32][33];
    int n0 = blockIdx.x * 32, k0 = blockIdx.y * 32;
    int x = threadIdx.x & 31, y = threadIdx.x >> 5;   // 32 x 8
#pragma unroll
    for (int j = 0; j < 32; j += 8)
        t[y + j][x] = in[(size_t)(k0 + y + j) * N + n0 + x];
    __syncthreads();
#pragma unroll
    for (int j = 0; j < 32; j += 8)
        out[(size_t)(n0 + y + j) * K + k0 + x] = __float2half_rn(t[x][y + j]);
}

// ---------------- fp16 mma GEMM: C = A[M,K] @ Bt[N,K]^T + bias ------------
// BM=128, BN=256, BK=32, 4 stages, 256 threads (8 warps 2x4), warp tile 64x64.
// Smem rows: 32 k-halves (64B data) padded to 80B -> conflict-free frag loads.
#define RSTR 80                       // smem row stride, bytes
#define A_BYTES (128 * RSTR)          // 10240
#define B_BYTES (256 * RSTR)          // 20480
#define STG_BYTES (A_BYTES + B_BYTES) // 30720
#define NSTAGE 4

template <int ACT, int RES, int OUTH, int ROUND>
__global__ __launch_bounds__(256, 1)
void gemm_h(const __half* __restrict__ A, const __half* __restrict__ Bt,
            const float* __restrict__ bias, const float* __restrict__ res,
            void* __restrict__ Cv, int M, int N, int K)
{
    extern __shared__ __align__(16) char smem[];
    const uint32_t sb = smem_u32(smem);
    const int tid = threadIdx.x;
    const int wid = tid >> 5, lane = tid & 31;
    const int g = lane >> 2, t = lane & 3;
    const int warp_m = (wid >> 2) * 64;   // 0 or 64
    const int warp_n = (wid & 3) * 64;    // 0..192
    const int m0 = blockIdx.y * 128;
    const int n0 = blockIdx.x * 256;
    const int nk = K / 32;

    float c[4][8][4];
#pragma unroll
    for (int mt = 0; mt < 4; mt++)
#pragma unroll
        for (int nt = 0; nt < 8; nt++)
#pragma unroll
            for (int i = 0; i < 4; i++) c[mt][nt][i] = 0.f;

    auto load_tile = [&](int stage, int k0) {
        uint32_t sA = sb + (uint32_t)stage * STG_BYTES;
        uint32_t sB = sA + A_BYTES;
#pragma unroll
        for (int cc = 0; cc < 2; cc++) {             // A: 128 rows x 4 chunks
            int idx = tid + cc * 256;
            int row = idx >> 2, off = idx & 3;
            CP_ASYNC16(sA + (uint32_t)row * RSTR + (uint32_t)off * 16,
                       (const char*)(A + (size_t)(m0 + row) * K + k0) + off * 16);
        }
#pragma unroll
        for (int cc = 0; cc < 4; cc++) {             // B: 256 rows x 4 chunks
            int idx = tid + cc * 256;
            int row = idx >> 2, off = idx & 3;
            CP_ASYNC16(sB + (uint32_t)row * RSTR + (uint32_t)off * 16,
                       (const char*)(Bt + (size_t)(n0 + row) * K + k0) + off * 16);
        }
    };

    int k0 = 0;
#pragma unroll
    for (int s = 0; s < NSTAGE - 1; s++) {
        load_tile(s, k0);
        CP_COMMIT();
        k0 += 32;
    }

    for (int it = 0; it < nk; it++) {
        CP_WAIT2();
        __syncthreads();
        const int cur = it & (NSTAGE - 1);
        if (k0 < K) {
            load_tile((it + NSTAGE - 1) & (NSTAGE - 1), k0);
            k0 += 32;
        }
        CP_COMMIT();

        const char* As = smem + (size_t)cur * STG_BYTES;
        const char* Bs = As + A_BYTES;

#pragma unroll
        for (int kk = 0; kk < 2; kk++) {         // two k16 steps per k32 tile
            const int kb = kk * 32;              // byte offset of k16 group
            uint32_t a[4][4], b[8][2];
#pragma unroll
            for (int mt = 0; mt < 4; mt++) {
                const char* ap = As + (warp_m + mt * 16 + g) * RSTR + kb + 4 * t;
                a[mt][0] = *(const uint32_t*)(ap);
                a[mt][1] = *(const uint32_t*)(ap + 8 * RSTR);
                a[mt][2] = *(const uint32_t*)(ap + 16);
                a[mt][3] = *(const uint32_t*)(ap + 8 * RSTR + 16);
            }
#pragma unroll
            for (int nt = 0; nt < 8; nt++) {
                const char* bp = Bs + (warp_n + nt * 8 + g) * RSTR + kb + 4 * t;
                b[nt][0] = *(const uint32_t*)(bp);
                b[nt][1] = *(const uint32_t*)(bp + 16);
            }
#pragma unroll
            for (int mt = 0; mt < 4; mt++)
#pragma unroll
                for (int nt = 0; nt < 8; nt++)
                    mma_f16(c[mt][nt], a[mt], b[nt]);
        }
    }

    // ---- epilogue ----
#pragma unroll
    for (int mt = 0; mt < 4; mt++) {
        const int rm = m0 + warp_m + mt * 16 + g;
#pragma unroll
        for (int nt = 0; nt < 8; nt++) {
            const int cn = n0 + warp_n + nt * 8 + 2 * t;
            float2 bv = *(const float2*)(bias + cn);
            float v0 = c[mt][nt][0] + bv.x;
            float v1 = c[mt][nt][1] + bv.y;
            float v2 = c[mt][nt][2] + bv.x;
            float v3 = c[mt][nt][3] + bv.y;
            if (RES) {
                float2 r0 = *(const float2*)(res + (size_t)rm * N + cn);
                float2 r1 = *(const float2*)(res + (size_t)(rm + 8) * N + cn);
                v0 += r0.x; v1 += r0.y; v2 += r1.x; v3 += r1.y;
            }
            if (ACT) {
                v0 = v0 / (1.f + __expf(-1.702f * v0));
                v1 = v1 / (1.f + __expf(-1.702f * v1));
                v2 = v2 / (1.f + __expf(-1.702f * v2));
                v3 = v3 / (1.f + __expf(-1.702f * v3));
            }
            if (OUTH) {
                __half* C = (__half*)Cv;
                *(__half2*)(C + (size_t)rm * N + cn) =
                    __halves2half2(__float2half_rn(v0), __float2half_rn(v1));
                *(__half2*)(C + (size_t)(rm + 8) * N + cn) =
                    __halves2half2(__float2half_rn(v2), __float2half_rn(v3));
            } else {
                float* C = (float*)Cv;
                if (ROUND) {
                    v0 = tf32r(v0); v1 = tf32r(v1); v2 = tf32r(v2); v3 = tf32r(v3);
                }
                *(float2*)(C + (size_t)rm * N + cn)       = make_float2(v0, v1);
                *(float2*)(C + (size_t)(rm + 8) * N + cn) = make_float2(v2, v3);
            }
        }
    }
}

// ---------------- LayerNorm (fp16 output) ----------------
__global__ __launch_bounds__(256) void ln_kernel(
    const float* __restrict__ x, const float* __restrict__ sc,
    const float* __restrict__ bi, __half* __restrict__ out)
{
    int row = blockIdx.x;
    const float* xr = x + row * DMODEL;
    __half* orow = out + (size_t)row * DMODEL;
    int t = threadIdx.x;
    float v[5];
    float s = 0.f, s2 = 0.f;
#pragma unroll
    for (int i = 0; i < 5; i++) {
        v[i] = xr[t + i * 256];
        s += v[i];
        s2 = fmaf(v[i], v[i], s2);
    }
    __shared__ float rs[8], rs2[8];
#pragma unroll
    for (int o = 16; o; o >>= 1) {
        s  += __shfl_xor_sync(0xffffffffu, s, o);
        s2 += __shfl_xor_sync(0xffffffffu, s2, o);
    }
    if ((t & 31) == 0) { rs[t >> 5] = s; rs2[t >> 5] = s2; }
    __syncthreads();
    if (t < 32) {
        float a = (t < 8) ? rs[t] : 0.f;
        float b = (t < 8) ? rs2[t] : 0.f;
#pragma unroll
        for (int o = 4; o; o >>= 1) {
            a += __shfl_xor_sync(0xffffffffu, a, o);
            b += __shfl_xor_sync(0xffffffffu, b, o);
        }
        if (t == 0) { rs[0] = a; rs2[0] = b; }
    }
    __syncthreads();
    float mu = rs[0] * (1.f / DMODEL);
    float var = rs2[0] * (1.f / DMODEL) - mu * mu;
    float inv = rsqrtf(var + 1e-6f);
#pragma unroll
    for (int i = 0; i < 5; i++) {
        int c = t + i * 256;
        orow[c] = __float2half_rn((v[i] - mu) * inv * sc[c] + bi[c]);
    }
}

// ---------------- RoPE on q and k in-place (tf32-rounded, fp32 buf) ------
__global__ __launch_bounds__(256) void rope_kernel(
    float* __restrict__ qkv, const float* __restrict__ rot)
{
    int idx = blockIdx.x * 256 + threadIdx.x;
    const int total = S_LEN * 2 * NHEAD * 40;
    if (idx >= total) return;
    int i = idx % 40;
    int h = (idx / 40) % NHEAD;
    int w = (idx / (40 * NHEAD)) % 2;
    int s = idx / (40 * NHEAD * 2);
    float* p = qkv + (size_t)s * (3 * DMODEL) + w * DMODEL + h * HDIM;
    float x1 = p[i];
    float x2 = p[i + 40];
    float f1 = rot[s * 40 + (i >> 1)];
    float f2 = rot[s * 40 + 20 + (i >> 1)];
    float c1, s1, c2, s2v;
    sincosf(f1, &s1, &c1);
    sincosf(f2, &s2v, &c2);
    p[i]      = tf32r(x1 * c1 - x2 * s1);
    p[i + 40] = tf32r(x2 * c2 + x1 * s2v);
}

// ---------------- Flash attention, tf32 mma (block-diag segments) ---------
// Unchanged math; output now fp16 for the proj GEMM.
#define QKSTR 84
#define VSTRD 88
#define PSTRD 68
#define OFF_QP 0
#define OFF_K0 5376
#define OFF_K1 10752
#define OFF_V0 16128
#define OFF_V1 21760
#define ATTN_SMEM_FLOATS 27392

__global__ __launch_bounds__(128, 1) void attn_mma_kernel(
    const float* __restrict__ qkv, const int* __restrict__ cu,
    int nseg, __half* __restrict__ out)
{
    extern __shared__ __align__(16) float sm[];
    const uint32_t sb = smem_u32(sm);
    const int tid = threadIdx.x;
    const int warp = tid >> 5, lane = tid & 31;
    const int g = lane >> 2, t = lane & 3;
    const int h = blockIdx.y;
    const int q0 = blockIdx.x * 64;
    const int w16 = warp * 16;

    int start = 0, end = S_LEN;
    for (int i = 0; i < nseg; i++) {
        int a = cu[i], b = cu[i + 1];
        if (q0 >= a && q0 < b) { start = a; end = b; break; }
    }
    const int L = end - start;
    const int ntiles = (L + 63) >> 6;

    for (int i = tid; i < 64 * 20; i += 128) {
        int row = i / 20, c = i % 20;
        *(float4*)(sm + OFF_QP + row * QKSTR + c * 4) =
            *(const float4*)(qkv + (size_t)(q0 + row) * (3 * DMODEL) + h * HDIM + c * 4);
    }
    __syncthreads();
    uint32_t qf[10][4];
#pragma unroll
    for (int ks = 0; ks < 10; ks++) {
        const float* qp = sm + OFF_QP + (w16 + g) * QKSTR + ks * 8 + t;
        qf[ks][0] = __float_as_uint(qp[0]);
        qf[ks][2] = __float_as_uint(qp[4]);
        qf[ks][1] = __float_as_uint(qp[8 * QKSTR]);
        qf[ks][3] = __float_as_uint(qp[8 * QKSTR + 4]);
    }

    auto load_kv = [&](int stage, int k0) {
        const uint32_t kBase = sb + (stage ? OFF_K1 : OFF_K0) * 4;
        const uint32_t vBase = sb + (stage ? OFF_V1 : OFF_V0) * 4;
        for (int i = tid; i < 64 * 20; i += 128) {
            int row = i / 20, c = i % 20;
            int key = k0 + row;
            int src = start + (key < L ? key : L - 1);
            const char* kg = (const char*)(qkv + (size_t)src * (3 * DMODEL) + DMODEL + h * HDIM + c * 4);
            const char* vg = (const char*)(qkv + (size_t)src * (3 * DMODEL) + 2 * DMODEL + h * HDIM + c * 4);
            CP_ASYNC16(kBase + ((uint32_t)row * QKSTR + (uint32_t)c * 4) * 4, kg);
            CP_ASYNC16(vBase + ((uint32_t)row * VSTRD + (uint32_t)c * 4) * 4, vg);
        }
    };

    load_kv(0, 0);
    CP_COMMIT();

    const float scale = 0.111803398875f;   // 1/sqrt(80)
    float m[2] = {-1e30f, -1e30f};
    float l[2] = {0.f, 0.f};
    float o[10][4];
#pragma unroll
    for (int nt = 0; nt < 10; nt++)
#pragma unroll
        for (int i = 0; i < 4; i++) o[nt][i] = 0.f;

    float* P = sm + OFF_QP;

    for (int kt = 0; kt < ntiles; kt++) {
        CP_WAIT0();
        __syncthreads();
        if (kt + 1 < ntiles) {
            load_kv((kt + 1) & 1, (kt + 1) * 64);
            CP_COMMIT();
        }
        const float* K = sm + ((kt & 1) ? OFF_K1 : OFF_K0);
        const float* V = sm + ((kt & 1) ? OFF_V1 : OFF_V0);

        float s[8][4];
#pragma unroll
        for (int nt = 0; nt < 8; nt++)
#pragma unroll
            for (int i = 0; i < 4; i++) s[nt][i] = 0.f;
#pragma unroll
        for (int ks = 0; ks < 10; ks++) {
            uint32_t b[8][2];
#pragma unroll
            for (int nt = 0; nt < 8; nt++) {
                const float* kp = K + (nt * 8 + g) * QKSTR + ks * 8 + t;
                b[nt][0] = __float_as_uint(kp[0]);
                b[nt][1] = __float_as_uint(kp[4]);
            }
#pragma unroll
            for (int nt = 0; nt < 8; nt++)
                mma_tf32(s[nt], qf[ks], b[nt]);
        }

        const bool maskT = (kt == ntiles - 1) && (L & 63);
#pragma unroll
        for (int r = 0; r < 2; r++) {
            float mx = -1e30f;
#pragma unroll
            for (int nt = 0; nt < 8; nt++) {
                float v0 = s[nt][2 * r]     * scale;
                float v1 = s[nt][2 * r + 1] * scale;
                if (maskT) {
                    int col = kt * 64 + nt * 8 + 2 * t;
                    if (col >= L)     v0 = -1e30f;
                    if (col + 1 >= L) v1 = -1e30f;
                }
                s[nt][2 * r] = v0; s[nt][2 * r + 1] = v1;
                mx = fmaxf(mx, fmaxf(v0, v1));
            }
            mx = fmaxf(mx, __shfl_xor_sync(0xffffffffu, mx, 1));
            mx = fmaxf(mx, __shfl_xor_sync(0xffffffffu, mx, 2));
            float nm = fmaxf(m[r], mx);
            float fac = __expf(m[r] - nm);
            m[r] = nm;
            float sum = 0.f;
#pragma unroll
            for (int nt = 0; nt < 8; nt++) {
                float e0 = __expf(s[nt][2 * r] - nm);
                float e1 = __expf(s[nt][2 * r + 1] - nm);
                sum += e0 + e1;
                *(float2*)(P + (w16 + g + 8 * r) * PSTRD + nt * 8 + 2 * t) =
                    make_float2(e0, e1);
            }
            sum += __shfl_xor_sync(0xffffffffu, sum, 1);
            sum += __shfl_xor_sync(0xffffffffu, sum, 2);
            l[r] = l[r] * fac + sum;
#pragma unroll
            for (int nt = 0; nt < 10; nt++) {
                o[nt][2 * r] *= fac;
                o[nt][2 * r + 1] *= fac;
            }
        }
        __syncwarp();

#pragma unroll
        for (int ks = 0; ks < 8; ks++) {
            uint32_t a[4];
            const float* pp = P + (w16 + g) * PSTRD + ks * 8 + t;
            a[0] = __float_as_uint(pp[0]);
            a[2] = __float_as_uint(pp[4]);
            a[1] = __float_as_uint(pp[8 * PSTRD]);
            a[3] = __float_as_uint(pp[8 * PSTRD + 4]);
            uint32_t b[10][2];
#pragma unroll
            for (int nt = 0; nt < 10; nt++) {
                const float* vp = V + (ks * 8 + t) * VSTRD + nt * 8 + g;
                b[nt][0] = __float_as_uint(vp[0]);
                b[nt][1] = __float_as_uint(vp[4 * VSTRD]);
            }
#pragma unroll
            for (int nt = 0; nt < 10; nt++)
                mma_tf32(o[nt], a, b[nt]);
        }
        __syncwarp();
    }

    // ---- epilogue: normalize, store fp16 ----
#pragma unroll
    for (int r = 0; r < 2; r++) {
        float inv = 1.f / l[r];
        const int row = q0 + w16 + g + 8 * r;
#pragma unroll
        for (int nt = 0; nt < 10; nt++) {
            *(__half2*)(out + (size_t)row * DMODEL + h * HDIM + nt * 8 + 2 * t) =
                __halves2half2(__float2half_rn(o[nt][2 * r] * inv),
                               __float2half_rn(o[nt][2 * r + 1] * inv));
        }
    }
}

// ---------------- launch ----------------
static void* sym_addr(const void* sym)
{
    void* p = nullptr;
    cudaGetSymbolAddress(&p, sym);
    return p;
}

extern "C" void kernel_launch(void* const* d_in, const int* in_sizes, int n_in,
                              void* d_out, int out_size)
{
    const float* x        = (const float*)d_in[0];
    const float* rot      = (const float*)d_in[1];
    const float* ln1_s    = (const float*)d_in[2];
    const float* ln1_b    = (const float*)d_in[3];
    const float* ln2_s    = (const float*)d_in[4];
    const float* ln2_b    = (const float*)d_in[5];
    const float* qkv_w    = (const float*)d_in[6];
    const float* qkv_b    = (const float*)d_in[7];
    const float* proj_w   = (const float*)d_in[8];
    const float* proj_b   = (const float*)d_in[9];
    const float* fc1_w    = (const float*)d_in[10];
    const float* fc1_b    = (const float*)d_in[11];
    const float* fc2_w    = (const float*)d_in[12];
    const float* fc2_b    = (const float*)d_in[13];
    const int*   cu       = (const int*)d_in[14];
    float*       out      = (float*)d_out;
    const int    nseg     = in_sizes[14] - 1;

    __half* hh    = (__half*)sym_addr(g_hh);
    float*  qkv   = (float*)sym_addr(g_qkv);
    __half* attnh = (__half*)sym_addr(g_attnh);
    float*  x1    = (float*)sym_addr(g_x1);
    __half* ffh   = (__half*)sym_addr(g_ffh);
    __half* whqkv = (__half*)sym_addr(g_wh_qkv);
    __half* whprj = (__half*)sym_addr(g_wh_proj);
    __half* whfc1 = (__half*)sym_addr(g_wh_fc1);
    __half* whfc2 = (__half*)sym_addr(g_wh_fc2);

    const int attn_smem = ATTN_SMEM_FLOATS * (int)sizeof(float);   // 109568
    cudaFuncSetAttribute(attn_mma_kernel, cudaFuncAttributeMaxDynamicSharedMemorySize, attn_smem);
    const int gemm_smem = NSTAGE * STG_BYTES;  // 122880
    cudaFuncSetAttribute(gemm_h<0, 0, 0, 1>, cudaFuncAttributeMaxDynamicSharedMemorySize, gemm_smem);
    cudaFuncSetAttribute(gemm_h<0, 1, 0, 0>, cudaFuncAttributeMaxDynamicSharedMemorySize, gemm_smem);
    cudaFuncSetAttribute(gemm_h<1, 0, 1, 0>, cudaFuncAttributeMaxDynamicSharedMemorySize, gemm_smem);

    // 0) weight transpose+convert to fp16 [N][K]
    transpose_h<<<dim3(3 * DMODEL / 32, DMODEL / 32), 256>>>(qkv_w, whqkv, DMODEL, 3 * DMODEL);
    transpose_h<<<dim3(DMODEL / 32, DMODEL / 32), 256>>>(proj_w, whprj, DMODEL, DMODEL);
    transpose_h<<<dim3(FFDIM / 32, DMODEL / 32), 256>>>(fc1_w, whfc1, DMODEL, FFDIM);
    transpose_h<<<dim3(DMODEL / 32, FFDIM / 32), 256>>>(fc2_w, whfc2, FFDIM, DMODEL);

    // 1) LN1 (fp16 output)
    ln_kernel<<<S_LEN, 256>>>(x, ln1_s, ln1_b, hh);
    // 2) QKV = h @ qkv_w + b  (fp32 out, tf32-rounded for attention)
    gemm_h<0, 0, 0, 1><<<dim3(3 * DMODEL / 256, S_LEN / 128), 256, gemm_smem>>>(
        hh, whqkv, qkv_b, nullptr, qkv, S_LEN, 3 * DMODEL, DMODEL);
    // 3) RoPE (rounds q,k)
    {
        int total = S_LEN * 2 * NHEAD * 40;
        rope_kernel<<<(total + 255) / 256, 256>>>(qkv, rot);
    }
    // 4) flash attention -> fp16
    attn_mma_kernel<<<dim3(S_LEN / 64, NHEAD), 128, attn_smem>>>(qkv, cu, nseg, attnh);
    // 5) x1 = x + attn @ proj_w + proj_b  (fp32 out)
    gemm_h<0, 1, 0, 0><<<dim3(DMODEL / 256, S_LEN / 128), 256, gemm_smem>>>(
        attnh, whprj, proj_b, x, x1, S_LEN, DMODEL, DMODEL);
    // 6) LN2 (fp16 output)
    ln_kernel<<<S_LEN, 256>>>(x1, ln2_s, ln2_b, hh);
    // 7) ff = quick_gelu(h @ fc1_w + fc1_b)  (fp16 out)
    gemm_h<1, 0, 1, 0><<<dim3(FFDIM / 256, S_LEN / 128), 256, gemm_smem>>>(
        hh, whfc1, fc1_b, nullptr, ffh, S_LEN, FFDIM, DMODEL);
    // 8) out = x1 + ff @ fc2_w + fc2_b  (fp32 out)
    gemm_h<0, 1, 0, 0><<<dim3(DMODEL / 256, S_LEN / 128), 256, gemm_smem>>>(
        ffh, whfc2, fc2_b, x1, out, S_LEN, DMODEL, FFDIM);
}

// round 13
// speedup vs baseline: 7.3568x; 1.0670x over previous
#include <cuda_runtime.h>
#include <cuda_fp16.h>
#include <math.h>
#include <stdint.h>

#define S_LEN 3072
#define DMODEL 1280
#define NHEAD 16
#define HDIM 80
#define FFDIM 5120

// ---------------- scratch (device globals; no allocations allowed) ----------
__device__ __half g_hh[S_LEN * DMODEL];        // LN output (fp16)
__device__ float  g_qkv[S_LEN * 3 * DMODEL];   // QKV (fp32)
__device__ __half g_qh[S_LEN * DMODEL];        // rope'd Q (fp16)
__device__ __half g_kh[S_LEN * DMODEL];        // rope'd K (fp16)
__device__ __half g_vth[NHEAD * HDIM * S_LEN]; // V^T [h][d][s] (fp16)
__device__ __half g_attnh[S_LEN * DMODEL];     // attention output (fp16)
__device__ float  g_x1[S_LEN * DMODEL];        // x + proj(attn)  (fp32)
__device__ __half g_ffh[S_LEN * FFDIM];        // gelu(fc1) (fp16)
__device__ __half g_wh_qkv[3 * DMODEL * DMODEL];  // weights [N][K] fp16
__device__ __half g_wh_proj[DMODEL * DMODEL];
__device__ __half g_wh_fc1[FFDIM * DMODEL];
__device__ __half g_wh_fc2[DMODEL * FFDIM];

// ---------------- helpers ----------------
__device__ __forceinline__ uint32_t smem_u32(const void* p) {
    uint32_t a;
    asm("{ .reg .u64 t; cvta.to.shared.u64 t, %1; cvt.u32.u64 %0, t; }"
        : "=r"(a) : "l"(p));
    return a;
}

#define CP_ASYNC16(dst, src) \
    asm volatile("cp.async.cg.shared.global [%0], [%1], 16;" :: "r"(dst), "l"(src) : "memory")
#define CP_COMMIT() asm volatile("cp.async.commit_group;" ::: "memory")
#define CP_WAIT2()  asm volatile("cp.async.wait_group 2;" ::: "memory")
#define CP_WAIT0()  asm volatile("cp.async.wait_group 0;" ::: "memory")

// fp16 mma: D(f32) += A(f16 m16k16,row) * B(f16 k16n8,col)
__device__ __forceinline__ void mma_f16(float* c, const uint32_t* a, const uint32_t* b) {
    asm volatile(
        "mma.sync.aligned.m16n8k16.row.col.f32.f16.f16.f32 "
        "{%0,%1,%2,%3}, {%4,%5,%6,%7}, {%8,%9}, {%0,%1,%2,%3};"
        : "+f"(c[0]), "+f"(c[1]), "+f"(c[2]), "+f"(c[3])
        : "r"(a[0]), "r"(a[1]), "r"(a[2]), "r"(a[3]), "r"(b[0]), "r"(b[1]));
}

// ---------------- weight transpose + fp16 convert: in[K,N] -> out[N,K] ----
// 64x64 tiles: 256B coalesced reads, 128B half writes.
__global__ __launch_bounds__(256) void transpose_h64(
    const float* __restrict__ in, __half* __restrict__ out, int K, int N)
{
    __shared__ float t[64][65];
    int n0 = blockIdx.x * 64, k0 = blockIdx.y * 64;
    int tid = threadIdx.x;
#pragma unroll
    for (int it = 0; it < 16; it++) {
        int idx = tid + it * 256;
        int r = idx >> 6, c = idx & 63;
        t[r][c] = in[(size_t)(k0 + r) * N + n0 + c];
    }
    __syncthreads();
#pragma unroll
    for (int it = 0; it < 16; it++) {
        int idx = tid + it * 256;
        int j = idx >> 6, i = idx & 63;
        out[(size_t)(n0 + j) * K + k0 + i] = __float2half_rn(t[i][j]);
    }
}

// ---------------- fp16 mma GEMM: C = A[M,K] @ Bt[N,K]^T + bias ------------
// BM=128, BN=256, BK=32, 4 stages, 256 threads (8 warps 2x4), warp tile 64x64.
#define RSTR 80                       // smem row stride, bytes
#define A_BYTES (128 * RSTR)          // 10240
#define B_BYTES (256 * RSTR)          // 20480
#define STG_BYTES (A_BYTES + B_BYTES) // 30720
#define NSTAGE 4

template <int ACT, int RES, int OUTH>
__global__ __launch_bounds__(256, 1)
void gemm_h(const __half* __restrict__ A, const __half* __restrict__ Bt,
            const float* __restrict__ bias, const float* __restrict__ res,
            void* __restrict__ Cv, int M, int N, int K)
{
    extern __shared__ __align__(16) char smem[];
    const uint32_t sb = smem_u32(smem);
    const int tid = threadIdx.x;
    const int wid = tid >> 5, lane = tid & 31;
    const int g = lane >> 2, t = lane & 3;
    const int warp_m = (wid >> 2) * 64;
    const int warp_n = (wid & 3) * 64;
    const int m0 = blockIdx.y * 128;
    const int n0 = blockIdx.x * 256;
    const int nk = K / 32;

    float c[4][8][4];
#pragma unroll
    for (int mt = 0; mt < 4; mt++)
#pragma unroll
        for (int nt = 0; nt < 8; nt++)
#pragma unroll
            for (int i = 0; i < 4; i++) c[mt][nt][i] = 0.f;

    auto load_tile = [&](int stage, int k0) {
        uint32_t sA = sb + (uint32_t)stage * STG_BYTES;
        uint32_t sB = sA + A_BYTES;
#pragma unroll
        for (int cc = 0; cc < 2; cc++) {
            int idx = tid + cc * 256;
            int row = idx >> 2, off = idx & 3;
            CP_ASYNC16(sA + (uint32_t)row * RSTR + (uint32_t)off * 16,
                       (const char*)(A + (size_t)(m0 + row) * K + k0) + off * 16);
        }
#pragma unroll
        for (int cc = 0; cc < 4; cc++) {
            int idx = tid + cc * 256;
            int row = idx >> 2, off = idx & 3;
            CP_ASYNC16(sB + (uint32_t)row * RSTR + (uint32_t)off * 16,
                       (const char*)(Bt + (size_t)(n0 + row) * K + k0) + off * 16);
        }
    };

    int k0 = 0;
#pragma unroll
    for (int s = 0; s < NSTAGE - 1; s++) {
        load_tile(s, k0);
        CP_COMMIT();
        k0 += 32;
    }

    for (int it = 0; it < nk; it++) {
        CP_WAIT2();
        __syncthreads();
        const int cur = it & (NSTAGE - 1);
        if (k0 < K) {
            load_tile((it + NSTAGE - 1) & (NSTAGE - 1), k0);
            k0 += 32;
        }
        CP_COMMIT();

        const char* As = smem + (size_t)cur * STG_BYTES;
        const char* Bs = As + A_BYTES;

#pragma unroll
        for (int kk = 0; kk < 2; kk++) {
            const int kb = kk * 32;
            uint32_t a[4][4], b[8][2];
#pragma unroll
            for (int mt = 0; mt < 4; mt++) {
                const char* ap = As + (warp_m + mt * 16 + g) * RSTR + kb + 4 * t;
                a[mt][0] = *(const uint32_t*)(ap);
                a[mt][1] = *(const uint32_t*)(ap + 8 * RSTR);
                a[mt][2] = *(const uint32_t*)(ap + 16);
                a[mt][3] = *(const uint32_t*)(ap + 8 * RSTR + 16);
            }
#pragma unroll
            for (int nt = 0; nt < 8; nt++) {
                const char* bp = Bs + (warp_n + nt * 8 + g) * RSTR + kb + 4 * t;
                b[nt][0] = *(const uint32_t*)(bp);
                b[nt][1] = *(const uint32_t*)(bp + 16);
            }
#pragma unroll
            for (int mt = 0; mt < 4; mt++)
#pragma unroll
                for (int nt = 0; nt < 8; nt++)
                    mma_f16(c[mt][nt], a[mt], b[nt]);
        }
    }

#pragma unroll
    for (int mt = 0; mt < 4; mt++) {
        const int rm = m0 + warp_m + mt * 16 + g;
#pragma unroll
        for (int nt = 0; nt < 8; nt++) {
            const int cn = n0 + warp_n + nt * 8 + 2 * t;
            float2 bv = *(const float2*)(bias + cn);
            float v0 = c[mt][nt][0] + bv.x;
            float v1 = c[mt][nt][1] + bv.y;
            float v2 = c[mt][nt][2] + bv.x;
            float v3 = c[mt][nt][3] + bv.y;
            if (RES) {
                float2 r0 = *(const float2*)(res + (size_t)rm * N + cn);
                float2 r1 = *(const float2*)(res + (size_t)(rm + 8) * N + cn);
                v0 += r0.x; v1 += r0.y; v2 += r1.x; v3 += r1.y;
            }
            if (ACT) {
                v0 = v0 / (1.f + __expf(-1.702f * v0));
                v1 = v1 / (1.f + __expf(-1.702f * v1));
                v2 = v2 / (1.f + __expf(-1.702f * v2));
                v3 = v3 / (1.f + __expf(-1.702f * v3));
            }
            if (OUTH) {
                __half* C = (__half*)Cv;
                *(__half2*)(C + (size_t)rm * N + cn) =
                    __halves2half2(__float2half_rn(v0), __float2half_rn(v1));
                *(__half2*)(C + (size_t)(rm + 8) * N + cn) =
                    __halves2half2(__float2half_rn(v2), __float2half_rn(v3));
            } else {
                float* C = (float*)Cv;
                *(float2*)(C + (size_t)rm * N + cn)       = make_float2(v0, v1);
                *(float2*)(C + (size_t)(rm + 8) * N + cn) = make_float2(v2, v3);
            }
        }
    }
}

// ---------------- LayerNorm (fp16 output) ----------------
__global__ __launch_bounds__(256) void ln_kernel(
    const float* __restrict__ x, const float* __restrict__ sc,
    const float* __restrict__ bi, __half* __restrict__ out)
{
    int row = blockIdx.x;
    const float* xr = x + row * DMODEL;
    __half* orow = out + (size_t)row * DMODEL;
    int t = threadIdx.x;
    float v[5];
    float s = 0.f, s2 = 0.f;
#pragma unroll
    for (int i = 0; i < 5; i++) {
        v[i] = xr[t + i * 256];
        s += v[i];
        s2 = fmaf(v[i], v[i], s2);
    }
    __shared__ float rs[8], rs2[8];
#pragma unroll
    for (int o = 16; o; o >>= 1) {
        s  += __shfl_xor_sync(0xffffffffu, s, o);
        s2 += __shfl_xor_sync(0xffffffffu, s2, o);
    }
    if ((t & 31) == 0) { rs[t >> 5] = s; rs2[t >> 5] = s2; }
    __syncthreads();
    if (t < 32) {
        float a = (t < 8) ? rs[t] : 0.f;
        float b = (t < 8) ? rs2[t] : 0.f;
#pragma unroll
        for (int o = 4; o; o >>= 1) {
            a += __shfl_xor_sync(0xffffffffu, a, o);
            b += __shfl_xor_sync(0xffffffffu, b, o);
        }
        if (t == 0) { rs[0] = a; rs2[0] = b; }
    }
    __syncthreads();
    float mu = rs[0] * (1.f / DMODEL);
    float var = rs2[0] * (1.f / DMODEL) - mu * mu;
    float inv = rsqrtf(var + 1e-6f);
#pragma unroll
    for (int i = 0; i < 5; i++) {
        int c = t + i * 256;
        orow[c] = __float2half_rn((v[i] - mu) * inv * sc[c] + bi[c]);
    }
}

// ---------------- RoPE: q,k fp32 -> rotated fp16 buffers ----------------
__global__ __launch_bounds__(256) void rope_h_kernel(
    const float* __restrict__ qkv, const float* __restrict__ rot,
    __half* __restrict__ qh, __half* __restrict__ kh)
{
    int idx = blockIdx.x * 256 + threadIdx.x;
    const int total = S_LEN * 2 * NHEAD * 40;
    if (idx >= total) return;
    int i = idx % 40;
    int h = (idx / 40) % NHEAD;
    int w = (idx / (40 * NHEAD)) % 2;
    int s = idx / (40 * NHEAD * 2);
    const float* p = qkv + (size_t)s * (3 * DMODEL) + w * DMODEL + h * HDIM;
    __half* dst = (w == 0 ? qh : kh) + (size_t)s * DMODEL + h * HDIM;
    float x1 = p[i];
    float x2 = p[i + 40];
    float f1 = rot[s * 40 + (i >> 1)];
    float f2 = rot[s * 40 + 20 + (i >> 1)];
    float c1, s1, c2, s2v;
    sincosf(f1, &s1, &c1);
    sincosf(f2, &s2v, &c2);
    dst[i]      = __float2half_rn(x1 * c1 - x2 * s1);
    dst[i + 40] = __float2half_rn(x2 * c2 + x1 * s2v);
}

// ---------------- V transpose: qkv fp32 [s][v:h*80+d] -> vth fp16 [h][d][s]
__global__ __launch_bounds__(256) void vtrans_kernel(
    const float* __restrict__ qkv, __half* __restrict__ vth)
{
    __shared__ float t[HDIM][65];
    int s0 = blockIdx.x * 64;
    int h = blockIdx.y;
    int tid = threadIdx.x;
#pragma unroll
    for (int it = 0; it < 20; it++) {
        int idx = tid + it * 256;
        int sl = idx / 80, d = idx % 80;
        t[d][sl] = qkv[(size_t)(s0 + sl) * (3 * DMODEL) + 2 * DMODEL + h * HDIM + d];
    }
    __syncthreads();
#pragma unroll
    for (int it = 0; it < 20; it++) {
        int idx = tid + it * 256;
        int d = idx >> 6, sl = idx & 63;
        vth[(size_t)(h * HDIM + d) * S_LEN + s0 + sl] = __float2half_rn(t[d][sl]);
    }
}

// ---------------- fp16 flash attention (block-diag segments) --------------
// Block: 64 queries x 1 head, 128 threads (4 warps x 16 q-rows each).
// K-tiles of 64 keys, double-buffered cp.async, online softmax, all fp16 mma.
#define AQSTR 176   // Q/K smem row stride, bytes (88 halves)
#define AVSTR 144   // VT & P smem row stride, bytes (72 halves)
#define AOFF_Q  0
#define AOFF_K0 11264
#define AOFF_K1 22528
#define AOFF_V0 33792
#define AOFF_V1 45312
#define ATTN_SMEM_BYTES 56832

__global__ __launch_bounds__(128, 1) void attn_h_kernel(
    const __half* __restrict__ qh, const __half* __restrict__ kh,
    const __half* __restrict__ vth, const int* __restrict__ cu,
    int nseg, __half* __restrict__ out)
{
    extern __shared__ __align__(16) char sm[];
    const uint32_t sb = smem_u32(sm);
    const int tid = threadIdx.x;
    const int warp = tid >> 5, lane = tid & 31;
    const int g = lane >> 2, t = lane & 3;
    const int h = blockIdx.y;
    const int q0 = blockIdx.x * 64;
    const int w16 = warp * 16;

    int start = 0, end = S_LEN;
    for (int i = 0; i < nseg; i++) {
        int a = cu[i], b = cu[i + 1];
        if (q0 >= a && q0 < b) { start = a; end = b; break; }
    }
    const int L = end - start;
    const int ntiles = (L + 63) >> 6;

    // ---- Q tile (cp.async): 64 rows x 160B ----
    for (int i = tid; i < 640; i += 128) {
        int row = i / 10, c = i % 10;
        CP_ASYNC16(sb + AOFF_Q + (uint32_t)row * AQSTR + (uint32_t)c * 16,
                   (const char*)(qh + (size_t)(q0 + row) * DMODEL + h * HDIM) + c * 16);
    }
    CP_COMMIT();

    auto load_kv = [&](int stage, int k0) {
        const uint32_t kBase = sb + (stage ? AOFF_K1 : AOFF_K0);
        const uint32_t vBase = sb + (stage ? AOFF_V1 : AOFF_V0);
        for (int i = tid; i < 640; i += 128) {
            int row = i / 10, c = i % 10;
            int key = k0 + row;
            int src = start + (key < L ? key : L - 1);
            CP_ASYNC16(kBase + (uint32_t)row * AQSTR + (uint32_t)c * 16,
                       (const char*)(kh + (size_t)src * DMODEL + h * HDIM) + c * 16);
        }
        for (int i = tid; i < 640; i += 128) {
            int d = i >> 3, c = i & 7;
            int kk0 = k0 + c * 8;
            if (kk0 + 8 > L) kk0 = L - 8;
            CP_ASYNC16(vBase + (uint32_t)d * AVSTR + (uint32_t)c * 16,
                       (const char*)(vth + (size_t)(h * HDIM + d) * S_LEN + start + kk0));
        }
    };

    load_kv(0, 0);
    CP_COMMIT();
    CP_WAIT0();
    __syncthreads();

    // ---- Q fragments to registers ----
    uint32_t qf[5][4];
#pragma unroll
    for (int ks = 0; ks < 5; ks++) {
        const char* qp = sm + AOFF_Q + (w16 + g) * AQSTR + ks * 32 + 4 * t;
        qf[ks][0] = *(const uint32_t*)(qp);
        qf[ks][1] = *(const uint32_t*)(qp + 8 * AQSTR);
        qf[ks][2] = *(const uint32_t*)(qp + 16);
        qf[ks][3] = *(const uint32_t*)(qp + 8 * AQSTR + 16);
    }
    __syncthreads();   // all warps have Q frags before P overwrites the region

    if (1 < ntiles) {  // prefetch tile 1
        load_kv(1, 64);
    }
    CP_COMMIT();

    const float scale = 0.111803398875f;   // 1/sqrt(80)
    float m[2] = {-1e30f, -1e30f};
    float l[2] = {0.f, 0.f};
    float o[10][4];
#pragma unroll
    for (int nt = 0; nt < 10; nt++)
#pragma unroll
        for (int i = 0; i < 4; i++) o[nt][i] = 0.f;

    char* Pb = sm + AOFF_Q;   // reuse Q region for P (per-warp rows)

    for (int kt = 0; kt < ntiles; kt++) {
        if (kt > 0) {
            CP_WAIT0();
            __syncthreads();
            if (kt + 1 < ntiles) {
                load_kv((kt + 1) & 1, (kt + 1) * 64);
            }
            CP_COMMIT();
        }
        const char* K = sm + ((kt & 1) ? AOFF_K1 : AOFF_K0);
        const char* V = sm + ((kt & 1) ? AOFF_V1 : AOFF_V0);

        // ---- S = Q K^T (fp16 mma, 5 ksteps) ----
        float s[8][4];
#pragma unroll
        for (int nt = 0; nt < 8; nt++)
#pragma unroll
            for (int i = 0; i < 4; i++) s[nt][i] = 0.f;
#pragma unroll
        for (int ks = 0; ks < 5; ks++) {
            uint32_t b[8][2];
#pragma unroll
            for (int nt = 0; nt < 8; nt++) {
                const char* kp = K + (nt * 8 + g) * AQSTR + ks * 32 + 4 * t;
                b[nt][0] = *(const uint32_t*)(kp);
                b[nt][1] = *(const uint32_t*)(kp + 16);
            }
#pragma unroll
            for (int nt = 0; nt < 8; nt++)
                mma_f16(s[nt], qf[ks], b[nt]);
        }

        // ---- online softmax ----
        const bool maskT = (kt == ntiles - 1) && (L & 63);
#pragma unroll
        for (int r = 0; r < 2; r++) {
            float mx = -1e30f;
#pragma unroll
            for (int nt = 0; nt < 8; nt++) {
                float v0 = s[nt][2 * r]     * scale;
                float v1 = s[nt][2 * r + 1] * scale;
                if (maskT) {
                    int col = kt * 64 + nt * 8 + 2 * t;
                    if (col >= L)     v0 = -1e30f;
                    if (col + 1 >= L) v1 = -1e30f;
                }
                s[nt][2 * r] = v0; s[nt][2 * r + 1] = v1;
                mx = fmaxf(mx, fmaxf(v0, v1));
            }
            mx = fmaxf(mx, __shfl_xor_sync(0xffffffffu, mx, 1));
            mx = fmaxf(mx, __shfl_xor_sync(0xffffffffu, mx, 2));
            float nm = fmaxf(m[r], mx);
            float fac = __expf(m[r] - nm);
            m[r] = nm;
            float sum = 0.f;
#pragma unroll
            for (int nt = 0; nt < 8; nt++) {
                float e0 = __expf(s[nt][2 * r] - nm);
                float e1 = __expf(s[nt][2 * r + 1] - nm);
                sum += e0 + e1;
                *(__half2*)(Pb + (w16 + g + 8 * r) * AVSTR + (nt * 8 + 2 * t) * 2) =
                    __halves2half2(__float2half_rn(e0), __float2half_rn(e1));
            }
            sum += __shfl_xor_sync(0xffffffffu, sum, 1);
            sum += __shfl_xor_sync(0xffffffffu, sum, 2);
            l[r] = l[r] * fac + sum;
#pragma unroll
            for (int nt = 0; nt < 10; nt++) {
                o[nt][2 * r] *= fac;
                o[nt][2 * r + 1] *= fac;
            }
        }
        __syncwarp();

        // ---- O += P V (fp16 mma, 4 ksteps over 64 keys) ----
#pragma unroll
        for (int ks = 0; ks < 4; ks++) {
            uint32_t a[4];
            const char* pp = Pb + (w16 + g) * AVSTR + ks * 32 + 4 * t;
            a[0] = *(const uint32_t*)(pp);
            a[1] = *(const uint32_t*)(pp + 8 * AVSTR);
            a[2] = *(const uint32_t*)(pp + 16);
            a[3] = *(const uint32_t*)(pp + 8 * AVSTR + 16);
            uint32_t b[10][2];
#pragma unroll
            for (int nt = 0; nt < 10; nt++) {
                const char* vp = V + (nt * 8 + g) * AVSTR + ks * 32 + 4 * t;
                b[nt][0] = *(const uint32_t*)(vp);
                b[nt][1] = *(const uint32_t*)(vp + 16);
            }
#pragma unroll
            for (int nt = 0; nt < 10; nt++)
                mma_f16(o[nt], a, b[nt]);
        }
        __syncwarp();
    }

    // ---- epilogue: normalize, store fp16 ----
#pragma unroll
    for (int r = 0; r < 2; r++) {
        float inv = 1.f / l[r];
        const int row = q0 + w16 + g + 8 * r;
#pragma unroll
        for (int nt = 0; nt < 10; nt++) {
            *(__half2*)(out + (size_t)row * DMODEL + h * HDIM + nt * 8 + 2 * t) =
                __halves2half2(__float2half_rn(o[nt][2 * r] * inv),
                               __float2half_rn(o[nt][2 * r + 1] * inv));
        }
    }
}

// ---------------- launch ----------------
static void* sym_addr(const void* sym)
{
    void* p = nullptr;
    cudaGetSymbolAddress(&p, sym);
    return p;
}

extern "C" void kernel_launch(void* const* d_in, const int* in_sizes, int n_in,
                              void* d_out, int out_size)
{
    const float* x        = (const float*)d_in[0];
    const float* rot      = (const float*)d_in[1];
    const float* ln1_s    = (const float*)d_in[2];
    const float* ln1_b    = (const float*)d_in[3];
    const float* ln2_s    = (const float*)d_in[4];
    const float* ln2_b    = (const float*)d_in[5];
    const float* qkv_w    = (const float*)d_in[6];
    const float* qkv_b    = (const float*)d_in[7];
    const float* proj_w   = (const float*)d_in[8];
    const float* proj_b   = (const float*)d_in[9];
    const float* fc1_w    = (const float*)d_in[10];
    const float* fc1_b    = (const float*)d_in[11];
    const float* fc2_w    = (const float*)d_in[12];
    const float* fc2_b    = (const float*)d_in[13];
    const int*   cu       = (const int*)d_in[14];
    float*       out      = (float*)d_out;
    const int    nseg     = in_sizes[14] - 1;

    __half* hh    = (__half*)sym_addr(g_hh);
    float*  qkv   = (float*)sym_addr(g_qkv);
    __half* qh    = (__half*)sym_addr(g_qh);
    __half* kh    = (__half*)sym_addr(g_kh);
    __half* vth   = (__half*)sym_addr(g_vth);
    __half* attnh = (__half*)sym_addr(g_attnh);
    float*  x1    = (float*)sym_addr(g_x1);
    __half* ffh   = (__half*)sym_addr(g_ffh);
    __half* whqkv = (__half*)sym_addr(g_wh_qkv);
    __half* whprj = (__half*)sym_addr(g_wh_proj);
    __half* whfc1 = (__half*)sym_addr(g_wh_fc1);
    __half* whfc2 = (__half*)sym_addr(g_wh_fc2);

    cudaFuncSetAttribute(attn_h_kernel, cudaFuncAttributeMaxDynamicSharedMemorySize, ATTN_SMEM_BYTES);
    const int gemm_smem = NSTAGE * STG_BYTES;  // 122880
    cudaFuncSetAttribute(gemm_h<0, 0, 0>, cudaFuncAttributeMaxDynamicSharedMemorySize, gemm_smem);
    cudaFuncSetAttribute(gemm_h<0, 1, 0>, cudaFuncAttributeMaxDynamicSharedMemorySize, gemm_smem);
    cudaFuncSetAttribute(gemm_h<1, 0, 1>, cudaFuncAttributeMaxDynamicSharedMemorySize, gemm_smem);

    // 0) weight transpose+convert to fp16 [N][K]
    transpose_h64<<<dim3(3 * DMODEL / 64, DMODEL / 64), 256>>>(qkv_w, whqkv, DMODEL, 3 * DMODEL);
    transpose_h64<<<dim3(DMODEL / 64, DMODEL / 64), 256>>>(proj_w, whprj, DMODEL, DMODEL);
    transpose_h64<<<dim3(FFDIM / 64, DMODEL / 64), 256>>>(fc1_w, whfc1, DMODEL, FFDIM);
    transpose_h64<<<dim3(DMODEL / 64, FFDIM / 64), 256>>>(fc2_w, whfc2, FFDIM, DMODEL);

    // 1) LN1 (fp16 output)
    ln_kernel<<<S_LEN, 256>>>(x, ln1_s, ln1_b, hh);
    // 2) QKV = h @ qkv_w + b  (fp32 out)
    gemm_h<0, 0, 0><<<dim3(3 * DMODEL / 256, S_LEN / 128), 256, gemm_smem>>>(
        hh, whqkv, qkv_b, nullptr, qkv, S_LEN, 3 * DMODEL, DMODEL);
    // 3) RoPE -> fp16 q/k; V -> fp16 transposed
    {
        int total = S_LEN * 2 * NHEAD * 40;
        rope_h_kernel<<<(total + 255) / 256, 256>>>(qkv, rot, qh, kh);
        vtrans_kernel<<<dim3(S_LEN / 64, NHEAD), 256>>>(qkv, vth);
    }
    // 4) fp16 flash attention -> fp16
    attn_h_kernel<<<dim3(S_LEN / 64, NHEAD), 128, ATTN_SMEM_BYTES>>>(qh, kh, vth, cu, nseg, attnh);
    // 5) x1 = x + attn @ proj_w + proj_b  (fp32 out)
    gemm_h<0, 1, 0><<<dim3(DMODEL / 256, S_LEN / 128), 256, gemm_smem>>>(
        attnh, whprj, proj_b, x, x1, S_LEN, DMODEL, DMODEL);
    // 6) LN2 (fp16 output)
    ln_kernel<<<S_LEN, 256>>>(x1, ln2_s, ln2_b, hh);
    // 7) ff = quick_gelu(h @ fc1_w + fc1_b)  (fp16 out)
    gemm_h<1, 0, 1><<<dim3(FFDIM / 256, S_LEN / 128), 256, gemm_smem>>>(
        hh, whfc1, fc1_b, nullptr, ffh, S_LEN, FFDIM, DMODEL);
    // 8) out = x1 + ff @ fc2_w + fc2_b  (fp32 out)
    gemm_h<0, 1, 0><<<dim3(DMODEL / 256, S_LEN / 128), 256, gemm_smem>>>(
        ffh, whfc2, fc2_b, x1, out, S_LEN, DMODEL, FFDIM);
}